// round 13
// baseline (speedup 1.0000x reference)
#include <cuda_runtime.h>
#include <cuda_bf16.h>
#include <cstdint>

// Problem dims (fixed by reference)
#define NB 8
#define NP 64
#define NS 512
#define ND 1024
#define NL 64
#define BPD (NB * NP)   // 512
#define BSD (NB * NS)   // 4096

// ---------------- device scratch (static globals; no allocs allowed) ----------------
__device__ float g_pred[BPD * ND];
__device__ float g_hid[BSD * ND];     // span FFNN hidden
__device__ float g_hidp[BPD * ND];    // pred FFNN hidden
__device__ float g_psc[BPD];
__device__ float g_asc[BSD];
__device__ float g_p2[BPD * NL];
__device__ float g_s2[BSD * NL];
__device__ __nv_bfloat16 g_pred_h[BPD * ND], g_pred_l[BPD * ND];
__device__ __nv_bfloat16 g_span_h[BSD * ND], g_span_l[BSD * ND];
__device__ __nv_bfloat16 g_wp_h[ND * ND], g_wp_l[ND * ND];
__device__ __nv_bfloat16 g_wa_h[ND * ND], g_wa_l[ND * ND];
__device__ __nv_bfloat16 g_u_h[(size_t)BPD * NL * ND],  g_u_l[(size_t)BPD * NL * ND];  // [bp][l][e]

// ---------------- PTX helpers (plain sm_80+ features only) ----------------
__device__ __forceinline__ uint32_t smem_to_u32(const void* p) {
    uint32_t a;
    asm("{ .reg .u64 t; cvta.to.shared.u64 t, %1; cvt.u32.u64 %0, t; }" : "=r"(a) : "l"(p));
    return a;
}
__device__ __forceinline__ void ldm_x4(uint32_t* r, uint32_t a) {
    asm volatile("ldmatrix.sync.aligned.m8n8.x4.shared.b16 {%0,%1,%2,%3}, [%4];"
                 : "=r"(r[0]), "=r"(r[1]), "=r"(r[2]), "=r"(r[3]) : "r"(a));
}
__device__ __forceinline__ void ldm_x4_t(uint32_t* r, uint32_t a) {
    asm volatile("ldmatrix.sync.aligned.m8n8.x4.trans.shared.b16 {%0,%1,%2,%3}, [%4];"
                 : "=r"(r[0]), "=r"(r[1]), "=r"(r[2]), "=r"(r[3]) : "r"(a));
}
__device__ __forceinline__ void mma_bf16(float* c, const uint32_t* a, const uint32_t* b) {
    asm volatile("mma.sync.aligned.m16n8k16.row.col.f32.bf16.bf16.f32 "
                 "{%0,%1,%2,%3}, {%4,%5,%6,%7}, {%8,%9}, {%0,%1,%2,%3};"
                 : "+f"(c[0]), "+f"(c[1]), "+f"(c[2]), "+f"(c[3])
                 : "r"(a[0]), "r"(a[1]), "r"(a[2]), "r"(a[3]), "r"(b[0]), "r"(b[1]));
}
__device__ __forceinline__ void cp16(uint32_t d, const void* s) {
    asm volatile("cp.async.cg.shared.global [%0], [%1], 16;" :: "r"(d), "l"(s));
}
#define CP_COMMIT() asm volatile("cp.async.commit_group;" ::: "memory")

__device__ __forceinline__ uint32_t sw128(uint32_t o) { return o ^ ((o >> 3) & 0x70); }  // 128B rows
__device__ __forceinline__ uint32_t sw256(uint32_t o) { return o ^ ((o >> 4) & 0x70); }  // 256B rows

// pack two fp32 into bf16x2 hi, returning lo pair via out-param
__device__ __forceinline__ uint32_t split2(float x, float y, uint32_t& lo) {
    __nv_bfloat16 hx = __float2bfloat16(x), hy = __float2bfloat16(y);
    __nv_bfloat162 h2 = __halves2bfloat162(hx, hy);
    __nv_bfloat162 l2 = __halves2bfloat162(__float2bfloat16(x - __bfloat162float(hx)),
                                           __float2bfloat16(y - __bfloat162float(hy)));
    lo = *(uint32_t*)&l2;
    return *(uint32_t*)&h2;
}

// ================== generic chunk-64 path (128B rows) ==================
// Stage layout: Ah @0 (16KB), Al @16K, Bh @32K, Bl @32K+BROWS*128
template <int BROWS, int NT>
__device__ __forceinline__ void prefetch_c64(
    uint32_t st, const __nv_bfloat16* Ah, const __nv_bfloat16* Al,
    const __nv_bfloat16* Bh, const __nv_bfloat16* Bl, int ch, int tid)
{
    const int co = ch * 64;
#pragma unroll
    for (int i = tid; i < 1024; i += NT) {
        int r = i >> 3, sg = i & 7;
        uint32_t sw = sw128((uint32_t)(r * 128 + sg * 16));
        const size_t g = (size_t)r * ND + co + sg * 8;
        cp16(st + sw, Ah + g);
        cp16(st + 16384 + sw, Al + g);
    }
#pragma unroll
    for (int i = tid; i < BROWS * 8; i += NT) {
        int r = i >> 3, sg = i & 7;
        uint32_t sw = sw128((uint32_t)(r * 128 + sg * 16));
        const size_t g = (size_t)r * ND + co + sg * 8;
        cp16(st + 32768 + sw, Bh + g);
        cp16(st + 32768 + BROWS * 128 + sw, Bl + g);
    }
}

template <int MF, int NF, int BROWS>
__device__ __forceinline__ void mma_c64(float (&acc)[MF][NF][4], uint32_t st,
                                        int lane, int warpM, int warpN)
{
#pragma unroll
    for (int kk = 0; kk < 4; kk++) {
        uint32_t afH[MF][4], afL[MF][4];
#pragma unroll
        for (int mf = 0; mf < MF; mf++) {
            uint32_t row = warpM + mf * 16 + (lane & 15);
            uint32_t kb = kk * 16 + ((lane >> 4) << 3);
            uint32_t sw = sw128(row * 128 + kb * 2);
            ldm_x4(afH[mf], st + sw);
            ldm_x4(afL[mf], st + 16384 + sw);
        }
        uint32_t bfH[NF][2], bfL[NF][2];
#pragma unroll
        for (int nb = 0; nb < NF / 2; nb++) {
            uint32_t row = warpN + nb * 16 + (lane & 7) + ((lane >> 4) & 1) * 8;
            uint32_t kb = kk * 16 + ((lane >> 3) & 1) * 8;
            uint32_t sw = sw128(row * 128 + kb * 2);
            uint32_t t[4];
            ldm_x4(t, st + 32768 + sw);
            bfH[2 * nb][0] = t[0]; bfH[2 * nb][1] = t[1];
            bfH[2 * nb + 1][0] = t[2]; bfH[2 * nb + 1][1] = t[3];
            ldm_x4(t, st + 32768 + BROWS * 128 + sw);
            bfL[2 * nb][0] = t[0]; bfL[2 * nb][1] = t[1];
            bfL[2 * nb + 1][0] = t[2]; bfL[2 * nb + 1][1] = t[3];
        }
#pragma unroll
        for (int mf = 0; mf < MF; mf++)
#pragma unroll
            for (int nf = 0; nf < NF; nf++)
                mma_bf16(acc[mf][nf], afH[mf], bfH[nf]);
#pragma unroll
        for (int mf = 0; mf < MF; mf++)
#pragma unroll
            for (int nf = 0; nf < NF; nf++)
                mma_bf16(acc[mf][nf], afH[mf], bfL[nf]);
#pragma unroll
        for (int mf = 0; mf < MF; mf++)
#pragma unroll
            for (int nf = 0; nf < NF; nf++)
                mma_bf16(acc[mf][nf], afL[mf], bfH[nf]);
    }
}

// 16 chunks of K=64, STAGES-deep, one __syncthreads per chunk
template <int MF, int NF, int BROWS, int STAGES, int NT>
__device__ __forceinline__ void gemm_pipe_c64(
    float (&acc)[MF][NF][4],
    const __nv_bfloat16* Ah, const __nv_bfloat16* Al,
    const __nv_bfloat16* Bh, const __nv_bfloat16* Bl,
    uint32_t sm, int tid, int lane, int warpM, int warpN)
{
    const uint32_t STAGE = 32768u + 2u * BROWS * 128u;
#pragma unroll
    for (int s = 0; s < STAGES - 1; s++) {
        prefetch_c64<BROWS, NT>(sm + s * STAGE, Ah, Al, Bh, Bl, s, tid);
        CP_COMMIT();
    }
#pragma unroll 1
    for (int ch = 0; ch < 16; ch++) {
        asm volatile("cp.async.wait_group %0;" :: "n"(STAGES - 2));
        __syncthreads();
        int nx = ch + STAGES - 1;
        if (nx < 16)
            prefetch_c64<BROWS, NT>(sm + (uint32_t)(nx % STAGES) * STAGE, Ah, Al, Bh, Bl, nx, tid);
        CP_COMMIT();
        mma_c64<MF, NF, BROWS>(acc, sm + (uint32_t)(ch % STAGES) * STAGE, lane, warpM, warpN);
    }
}

// ---------------- FFNN last layer (merged pred+span): hid = relu(A @ W^T + bias) ----------------
// 512 threads, 16 warps in 4x4 grid, warp tile 32x32 (MF=2, NF=4)
__global__ __launch_bounds__(512, 1) void k_mma_ntrelu(const float* __restrict__ bpv,
                                                       const float* __restrict__ bav)
{
    extern __shared__ __align__(1024) char dsm[];
    const uint32_t sm = smem_to_u32(dsm);
    const int tid = threadIdx.x, lane = tid & 31, wid = tid >> 5;
    const int warpM = (wid >> 2) * 32, warpN = (wid & 3) * 32;
    const int isSpan = blockIdx.y >= 4;
    const int mBase = (isSpan ? (blockIdx.y - 4) : blockIdx.y) * 128;
    const int nBase = blockIdx.x * 128;
    const float* bias = isSpan ? bav : bpv;

    const __nv_bfloat16* Ah = (isSpan ? g_span_h : g_pred_h) + (size_t)mBase * ND;
    const __nv_bfloat16* Al = (isSpan ? g_span_l : g_pred_l) + (size_t)mBase * ND;
    const __nv_bfloat16* Wh = (isSpan ? g_wa_h : g_wp_h) + (size_t)nBase * ND;
    const __nv_bfloat16* Wl = (isSpan ? g_wa_l : g_wp_l) + (size_t)nBase * ND;
    float* hid = isSpan ? g_hid : g_hidp;

    float acc[2][4][4] = {};
    gemm_pipe_c64<2, 4, 128, 3, 512>(acc, Ah, Al, Wh, Wl, sm, tid, lane, warpM, warpN);

#pragma unroll
    for (int mf = 0; mf < 2; mf++)
#pragma unroll
        for (int h = 0; h < 2; h++) {
            int row = mBase + warpM + mf * 16 + (lane >> 2) + h * 8;
            float* orow = hid + (size_t)row * ND;
#pragma unroll
            for (int nf = 0; nf < 4; nf++) {
                int col = nBase + warpN + nf * 8 + (lane & 3) * 2;
                float2 v;
                v.x = fmaxf(acc[mf][nf][2 * h + 0] + bias[col], 0.f);
                v.y = fmaxf(acc[mf][nf][2 * h + 1] + bias[col + 1], 0.f);
                *(float2*)(orow + col) = v;
            }
        }
}

// ================== Stage 1 with fused W1 split (no k_w1t, no transposed copy) ==================
// U[bp, l, e] = sum_d pred[bp, d] * W1[l, d, e]
#define U_ASTAGE 32768u
#define U_BOFF   98304u
#define U_BBUF   32768u

template <int NT>
__device__ __forceinline__ void prefetch_A64(uint32_t st, const __nv_bfloat16* Ah,
                                             const __nv_bfloat16* Al, int ch, int tid)
{
    const int co = ch * 64;
#pragma unroll
    for (int i = tid; i < 1024; i += NT) {
        int r = i >> 3, sg = i & 7;
        uint32_t sw = sw128((uint32_t)(r * 128 + sg * 16));
        const size_t g = (size_t)r * ND + co + sg * 8;
        cp16(st + sw, Ah + g);
        cp16(st + 16384 + sw, Al + g);
    }
}

// 512 threads: each handles 2 row-groups of the 64x128 fp32 W1 chunk
__device__ __forceinline__ void ldgB(float4 (&b)[4], const float* Wl, int ch, int tid) {
#pragma unroll
    for (int j = 0; j < 2; j++) {
        int g = tid + 512 * j;
        int r = g >> 4, cg = g & 15;
        const float* s = Wl + (size_t)(ch * 64 + r) * ND + cg * 8;
        b[2 * j]     = *(const float4*)s;
        b[2 * j + 1] = *(const float4*)(s + 4);
    }
}

__device__ __forceinline__ void stsB(char* bbase, const float4 (&b)[4], int tid) {
#pragma unroll
    for (int j = 0; j < 2; j++) {
        int g = tid + 512 * j;
        int r = g >> 4, cg = g & 15;
        uint32_t sw = sw256((uint32_t)(r * 256 + cg * 16));
        uint4 hi, lo;
        hi.x = split2(b[2 * j].x,     b[2 * j].y,     lo.x);
        hi.y = split2(b[2 * j].z,     b[2 * j].w,     lo.y);
        hi.z = split2(b[2 * j + 1].x, b[2 * j + 1].y, lo.z);
        hi.w = split2(b[2 * j + 1].z, b[2 * j + 1].w, lo.w);
        *(uint4*)(bbase + sw) = hi;
        *(uint4*)(bbase + 16384 + sw) = lo;
    }
}

// B frags via ldmatrix.trans from K-major 256B-row tile
template <int MF, int NF>
__device__ __forceinline__ void mma_chunk_u(float (&acc)[MF][NF][4], uint32_t stA,
                                            uint32_t bB, int lane, int warpM, int warpN)
{
#pragma unroll
    for (int kk = 0; kk < 4; kk++) {
        uint32_t afH[MF][4], afL[MF][4];
#pragma unroll
        for (int mf = 0; mf < MF; mf++) {
            uint32_t row = warpM + mf * 16 + (lane & 15);
            uint32_t kb = kk * 16 + ((lane >> 4) << 3);
            uint32_t sw = sw128(row * 128 + kb * 2);
            ldm_x4(afH[mf], stA + sw);
            ldm_x4(afL[mf], stA + 16384 + sw);
        }
        uint32_t bfH[NF][2], bfL[NF][2];
#pragma unroll
        for (int nb = 0; nb < NF / 2; nb++) {
            uint32_t row = kk * 16 + ((lane >> 3) & 1) * 8 + (lane & 7);   // d within chunk
            uint32_t col = warpN + nb * 16 + ((lane >> 4) & 1) * 8;        // e within tile
            uint32_t sw = sw256(row * 256 + col * 2);
            uint32_t t[4];
            ldm_x4_t(t, bB + sw);
            bfH[2 * nb][0] = t[0]; bfH[2 * nb][1] = t[1];
            bfH[2 * nb + 1][0] = t[2]; bfH[2 * nb + 1][1] = t[3];
            ldm_x4_t(t, bB + 16384 + sw);
            bfL[2 * nb][0] = t[0]; bfL[2 * nb][1] = t[1];
            bfL[2 * nb + 1][0] = t[2]; bfL[2 * nb + 1][1] = t[3];
        }
#pragma unroll
        for (int mf = 0; mf < MF; mf++)
#pragma unroll
            for (int nf = 0; nf < NF; nf++)
                mma_bf16(acc[mf][nf], afH[mf], bfH[nf]);
#pragma unroll
        for (int mf = 0; mf < MF; mf++)
#pragma unroll
            for (int nf = 0; nf < NF; nf++)
                mma_bf16(acc[mf][nf], afH[mf], bfL[nf]);
#pragma unroll
        for (int mf = 0; mf < MF; mf++)
#pragma unroll
            for (int nf = 0; nf < NF; nf++)
                mma_bf16(acc[mf][nf], afL[mf], bfH[nf]);
    }
}

__global__ __launch_bounds__(512, 1) void k_u_mma(const float* __restrict__ W1)
{
    extern __shared__ __align__(1024) char dsm[];
    const uint32_t sm = smem_to_u32(dsm);
    const int tid = threadIdx.x, lane = tid & 31, wid = tid >> 5;
    const int warpM = (wid >> 2) * 32, warpN = (wid & 3) * 32;
    const int nBase = blockIdx.x * 128, mBase = blockIdx.y * 128, l = blockIdx.z;

    const __nv_bfloat16* Ah = g_pred_h + (size_t)mBase * ND;
    const __nv_bfloat16* Al = g_pred_l + (size_t)mBase * ND;
    const float* Wl = W1 + (size_t)l * ND * ND + nBase;   // + d*ND + e

    float4 breg[4];
    ldgB(breg, Wl, 0, tid);
    prefetch_A64<512>(sm + 0 * U_ASTAGE, Ah, Al, 0, tid); CP_COMMIT();
    prefetch_A64<512>(sm + 1 * U_ASTAGE, Ah, Al, 1, tid); CP_COMMIT();
    stsB(dsm + U_BOFF, breg, tid);

    float acc[2][4][4] = {};
#pragma unroll 1
    for (int ch = 0; ch < 16; ch++) {
        asm volatile("cp.async.wait_group 1;");
        __syncthreads();                              // publishes A(ch) + STS of B(ch)
        if (ch + 1 < 16) ldgB(breg, Wl, ch + 1, tid); // hidden under this chunk's MMA
        if (ch + 2 < 16) prefetch_A64<512>(sm + (uint32_t)((ch + 2) % 3) * U_ASTAGE, Ah, Al, ch + 2, tid);
        CP_COMMIT();
        mma_chunk_u<2, 4>(acc, sm + (uint32_t)(ch % 3) * U_ASTAGE,
                          sm + U_BOFF + (uint32_t)(ch & 1) * U_BBUF, lane, warpM, warpN);
        if (ch + 1 < 16) stsB(dsm + U_BOFF + (size_t)((ch + 1) & 1) * U_BBUF, breg, tid);
    }

#pragma unroll
    for (int mf = 0; mf < 2; mf++)
#pragma unroll
        for (int h = 0; h < 2; h++) {
            int row = mBase + warpM + mf * 16 + (lane >> 2) + h * 8;
            size_t base = ((size_t)row * NL + l) * ND;
#pragma unroll
            for (int nf = 0; nf < 4; nf++) {
                int col = nBase + warpN + nf * 8 + (lane & 3) * 2;
                float v0 = acc[mf][nf][2 * h + 0], v1 = acc[mf][nf][2 * h + 1];
                uint32_t lo2;
                uint32_t hi2 = split2(v0, v1, lo2);
                *(uint32_t*)(g_u_h + base + col) = hi2;
                *(uint32_t*)(g_u_l + base + col) = lo2;
            }
        }
}

// ---------------- Stage 2 + full epilogue -> scores ----------------
__global__ __launch_bounds__(256, 2) void k_final_mma(const float* __restrict__ bias,
                                                      float* __restrict__ out)
{
    extern __shared__ __align__(1024) char dsm[];
    const uint32_t sm = smem_to_u32(dsm);
    const int tid = threadIdx.x, lane = tid & 31, wid = tid >> 5;
    const int warpM = (wid >> 1) * 32, warpN = (wid & 1) * 32;
    const int mBase = blockIdx.x * 128, bp = blockIdx.y, b = bp >> 6;

    const __nv_bfloat16* Ah = g_span_h + ((size_t)b * NS + mBase) * ND;
    const __nv_bfloat16* Al = g_span_l + ((size_t)b * NS + mBase) * ND;
    const __nv_bfloat16* Bh = g_u_h + (size_t)bp * NL * ND;
    const __nv_bfloat16* Bl = g_u_l + (size_t)bp * NL * ND;

    float acc[2][4][4] = {};
    gemm_pipe_c64<2, 4, 64, 2, 256>(acc, Ah, Al, Bh, Bl, sm, tid, lane, warpM, warpN);

    const float* p2 = g_p2 + (size_t)bp * NL;
#pragma unroll
    for (int mf = 0; mf < 2; mf++)
#pragma unroll
        for (int h = 0; h < 2; h++) {
            int s = mBase + warpM + mf * 16 + (lane >> 2) + h * 8;
            size_t srow = (size_t)b * NS + s;
            float add = g_psc[bp] + g_asc[srow];
            const float* s2 = g_s2 + srow * NL;
            float* orow = out + ((size_t)bp * NS + s) * NL;
#pragma unroll
            for (int nf = 0; nf < 4; nf++) {
                int col = warpN + nf * 8 + (lane & 3) * 2;
                float2 v;
                v.x = acc[mf][nf][2 * h + 0] + p2[col] + s2[col] + bias[col] + add;
                v.y = acc[mf][nf][2 * h + 1] + p2[col + 1] + s2[col + 1] + bias[col + 1] + add;
                if (col + 1 == NL - 1) v.y = 0.f;   // null-label column
                *(float2*)(orow + col) = v;
            }
        }
}

// ---------------- gather predicate rows + bf16 split ----------------
__global__ __launch_bounds__(256) void k_gather_split(const float* __restrict__ span,
                                                      const int* __restrict__ preds) {
    int bp = blockIdx.x;
    int b = bp / NP;
    int s = preds[bp];
    float4 v = ((const float4*)(span + ((size_t)b * NS + s) * ND))[threadIdx.x];
    ((float4*)(g_pred + (size_t)bp * ND))[threadIdx.x] = v;
    uint32_t lo0, lo1;
    uint32_t hi0 = split2(v.x, v.y, lo0);
    uint32_t hi1 = split2(v.z, v.w, lo1);
    uint32_t* ph = (uint32_t*)(g_pred_h + (size_t)bp * ND);
    uint32_t* pl = (uint32_t*)(g_pred_l + (size_t)bp * ND);
    ph[threadIdx.x * 2 + 0] = hi0;
    ph[threadIdx.x * 2 + 1] = hi1;
    pl[threadIdx.x * 2 + 0] = lo0;
    pl[threadIdx.x * 2 + 1] = lo1;
}

// ---------------- merged fp32 -> (hi, lo) bf16 split for span + Wp + Wa ----------------
#define N4_SPAN (BSD * ND / 4)    // 1048576
#define N4_W    (ND * ND / 4)     // 262144
__global__ __launch_bounds__(256) void k_splitall(const float* __restrict__ span,
                                                  const float* __restrict__ Wp,
                                                  const float* __restrict__ Wa) {
    int i = blockIdx.x * 256 + threadIdx.x;
    const float* x;
    __nv_bfloat16 *H, *L;
    int j;
    if (i < N4_SPAN)                { x = span; j = i;                     H = g_span_h; L = g_span_l; }
    else if (i < N4_SPAN + N4_W)    { x = Wp;   j = i - N4_SPAN;           H = g_wp_h;   L = g_wp_l; }
    else if (i < N4_SPAN + 2*N4_W)  { x = Wa;   j = i - N4_SPAN - N4_W;    H = g_wa_h;   L = g_wa_l; }
    else return;
    float4 v = ((const float4*)x)[j];
    uint32_t lo0, lo1;
    uint32_t hi0 = split2(v.x, v.y, lo0);
    uint32_t hi1 = split2(v.z, v.w, lo1);
    ((uint32_t*)H)[2 * j + 0] = hi0;
    ((uint32_t*)H)[2 * j + 1] = hi1;
    ((uint32_t*)L)[2 * j + 0] = lo0;
    ((uint32_t*)L)[2 * j + 1] = lo1;
}

// ---------------- merged row dot ----------------
__global__ __launch_bounds__(256) void k_rowdot(const float* __restrict__ wp,
                                                const float* __restrict__ wa) {
    int r = blockIdx.x;
    const int isPred = r >= BSD;
    const float* Hp = isPred ? (g_hidp + (size_t)(r - BSD) * ND) : (g_hid + (size_t)r * ND);
    const float* w = isPred ? wp : wa;
    float s = 0.f;
    for (int j = threadIdx.x; j < ND; j += 256) s = fmaf(Hp[j], w[j], s);
    __shared__ float red[256];
    red[threadIdx.x] = s;
    __syncthreads();
    for (int o = 128; o > 0; o >>= 1) {
        if (threadIdx.x < o) red[threadIdx.x] += red[threadIdx.x + o];
        __syncthreads();
    }
    if (threadIdx.x == 0) {
        if (isPred) g_psc[r - BSD] = red[0];
        else        g_asc[r] = red[0];
    }
}

// ---------------- merged NN GEMM M x 64, K=1024 ----------------
__global__ __launch_bounds__(256) void k_gemm_nn64(const float* __restrict__ span,
                                                   const float* __restrict__ W2) {
    const int isSpan = blockIdx.y >= 8;
    const float* A = isSpan ? span : g_pred;
    const float* Bw = W2 + (isSpan ? (size_t)ND * NL : 0);
    float* C = isSpan ? g_s2 : g_p2;
    const int rowBase = (isSpan ? (blockIdx.y - 8) : blockIdx.y) * 64;

    __shared__ float As[16][64];
    __shared__ float Bs[16][64];
    const int tid = threadIdx.x;
    const int tx = tid & 15, ty = tid >> 4;
    const int alr = tid >> 2;
    const int alc = (tid & 3) << 2;
    const float* Ap = A + (size_t)(rowBase + alr) * ND + alc;
    const int blr = tid >> 4;
    const int blc = (tid & 15) << 2;
    const float* Bp = Bw + (size_t)blr * NL + blc;

    float acc[4][4];
#pragma unroll
    for (int i = 0; i < 4; i++)
#pragma unroll
        for (int j = 0; j < 4; j++) acc[i][j] = 0.f;

    for (int k0 = 0; k0 < ND; k0 += 16) {
        float4 av = *(const float4*)(Ap + k0);
        As[alc + 0][alr] = av.x;
        As[alc + 1][alr] = av.y;
        As[alc + 2][alr] = av.z;
        As[alc + 3][alr] = av.w;
        float4 bv = *(const float4*)(Bp + (size_t)k0 * NL);
        *(float4*)&Bs[blr][blc] = bv;
        __syncthreads();
#pragma unroll
        for (int k = 0; k < 16; k++) {
            float4 a4 = *(const float4*)&As[k][ty * 4];
            float4 b4 = *(const float4*)&Bs[k][tx * 4];
            float a[4] = {a4.x, a4.y, a4.z, a4.w};
            float bb[4] = {b4.x, b4.y, b4.z, b4.w};
#pragma unroll
            for (int i = 0; i < 4; i++)
#pragma unroll
                for (int j = 0; j < 4; j++)
                    acc[i][j] = fmaf(a[i], bb[j], acc[i][j]);
        }
        __syncthreads();
    }
#pragma unroll
    for (int i = 0; i < 4; i++) {
        int row = rowBase + ty * 4 + i;
        *(float4*)(C + (size_t)row * NL + tx * 4) =
            make_float4(acc[i][0], acc[i][1], acc[i][2], acc[i][3]);
    }
}

// ---------------- labels cast + tail zero ----------------
__global__ void k_labels(const int* __restrict__ lab, float* __restrict__ out, int n) {
    int i = blockIdx.x * blockDim.x + threadIdx.x;
    if (i < n) out[i] = (float)lab[i];
}
__global__ void k_zero(float* __restrict__ out, int n) {
    int i = blockIdx.x * blockDim.x + threadIdx.x;
    if (i < n) out[i] = 0.f;
}

// ---------------- host ----------------
extern "C" void kernel_launch(void* const* d_in, const int* in_sizes, int n_in,
                              void* d_out, int out_size)
{
    const float* span   = (const float*)d_in[0];
    const int*   preds  = (const int*)d_in[1];
    const int*   labels = (const int*)d_in[2];
    // d_in[3] = len_info (dense, unused)
    // FFNN bug: only the LAST layer (index 1) of each stack matters.
    const float* Wp   = (const float*)d_in[4] + (size_t)ND * ND;
    const float* bpv  = (const float*)d_in[5] + ND;
    const float* Wa   = (const float*)d_in[6] + (size_t)ND * ND;
    const float* bav  = (const float*)d_in[7] + ND;
    const float* wp   = (const float*)d_in[8];
    const float* wa   = (const float*)d_in[9];
    const float* W1   = (const float*)d_in[10];
    const float* W2   = (const float*)d_in[11];
    const float* bias = (const float*)d_in[12];
    float* out = (float*)d_out;

    // second stream + fork/join events (created once; host resources, no device mem)
    static cudaStream_t sB = nullptr;
    static cudaEvent_t eG = nullptr, eB = nullptr;
    if (sB == nullptr) {
        cudaStreamCreateWithFlags(&sB, cudaStreamNonBlocking);
        cudaEventCreateWithFlags(&eG, cudaEventDisableTiming);
        cudaEventCreateWithFlags(&eB, cudaEventDisableTiming);
    }

    const int SMEM_NT  = 196608;   // ntrelu: 3 x 64KB (1 CTA/SM)
    const int SMEM_U   = 163840;   // u_mma:  3x32KB A + 2x32KB B (1 CTA/SM)
    const int SMEM_FIN = 98304;    // final:  2 x 48KB (2 CTAs/SM)
    cudaFuncSetAttribute(k_mma_ntrelu, cudaFuncAttributeMaxDynamicSharedMemorySize, SMEM_NT);
    cudaFuncSetAttribute(k_u_mma,      cudaFuncAttributeMaxDynamicSharedMemorySize, SMEM_U);
    cudaFuncSetAttribute(k_final_mma,  cudaFuncAttributeMaxDynamicSharedMemorySize, SMEM_FIN);

    const int n_scores = NB * NP * NS * NL;
    const int n_lab = NB * NP * NS;

    // ---- stream 0 (capture stream): gather -> u_mma (the long pole) ----
    k_gather_split<<<BPD, 256>>>(span, preds);
    cudaEventRecord(eG, 0);
    k_u_mma<<<dim3(8, 4, 64), 512, SMEM_U>>>(W1);     // needs only pred_h/l + raw W1

    // ---- stream B: everything else, concurrent with u_mma ----
    cudaStreamWaitEvent(sB, eG, 0);
    k_splitall<<<(N4_SPAN + 2 * N4_W + 255) / 256, 256, 0, sB>>>(span, Wp, Wa);
    k_mma_ntrelu<<<dim3(8, 36), 512, SMEM_NT, sB>>>(bpv, bav);
    k_rowdot<<<BSD + BPD, 256, 0, sB>>>(wp, wa);
    k_gemm_nn64<<<dim3(1, 72), 256, 0, sB>>>(span, W2);
    if (out_size >= n_scores + n_lab)
        k_labels<<<(n_lab + 255) / 256, 256, 0, sB>>>(labels, out + n_scores, n_lab);
    {
        int written = (out_size >= n_scores + n_lab) ? n_scores + n_lab : n_scores;
        if (out_size > written) {
            int rem = out_size - written;
            k_zero<<<(rem + 255) / 256, 256, 0, sB>>>(out + written, rem);
        }
    }
    cudaEventRecord(eB, sB);

    // ---- join -> final ----
    cudaStreamWaitEvent(0, eB, 0);
    k_final_mma<<<dim3(4, 512), 256, SMEM_FIN>>>(bias, out);
}

// round 15
// speedup vs baseline: 1.3558x; 1.3558x over previous
#include <cuda_runtime.h>
#include <cuda_fp16.h>
#include <cstdint>

// Problem dims (fixed by reference)
#define NB 8
#define NP 64
#define NS 512
#define ND 1024
#define NL 64
#define BPD (NB * NP)   // 512
#define BSD (NB * NS)   // 4096

// ---------------- device scratch (static globals; no allocs allowed) ----------------
__device__ float g_pred[BPD * ND];
__device__ float g_hid[BSD * ND];     // span FFNN hidden
__device__ float g_hidp[BPD * ND];    // pred FFNN hidden
__device__ float g_psc[BPD];
__device__ float g_asc[BSD];
__device__ float g_p2[BPD * NL];
__device__ float g_s2[BSD * NL];
__device__ __half g_pred_h[BPD * ND], g_pred_l[BPD * ND];
__device__ __half g_span_h[BSD * ND], g_span_l[BSD * ND];
__device__ __half g_wp_h[ND * ND], g_wp_l[ND * ND];
__device__ __half g_wa_h[ND * ND], g_wa_l[ND * ND];
__device__ __half g_u[(size_t)BPD * NL * ND];   // U, fp16 hi only  [bp][l][e]

// ---------------- PTX helpers (plain sm_80+ features only) ----------------
__device__ __forceinline__ uint32_t smem_to_u32(const void* p) {
    uint32_t a;
    asm("{ .reg .u64 t; cvta.to.shared.u64 t, %1; cvt.u32.u64 %0, t; }" : "=r"(a) : "l"(p));
    return a;
}
__device__ __forceinline__ void ldm_x4(uint32_t* r, uint32_t a) {
    asm volatile("ldmatrix.sync.aligned.m8n8.x4.shared.b16 {%0,%1,%2,%3}, [%4];"
                 : "=r"(r[0]), "=r"(r[1]), "=r"(r[2]), "=r"(r[3]) : "r"(a));
}
__device__ __forceinline__ void ldm_x4_t(uint32_t* r, uint32_t a) {
    asm volatile("ldmatrix.sync.aligned.m8n8.x4.trans.shared.b16 {%0,%1,%2,%3}, [%4];"
                 : "=r"(r[0]), "=r"(r[1]), "=r"(r[2]), "=r"(r[3]) : "r"(a));
}
__device__ __forceinline__ void mma_f16(float* c, const uint32_t* a, const uint32_t* b) {
    asm volatile("mma.sync.aligned.m16n8k16.row.col.f32.f16.f16.f32 "
                 "{%0,%1,%2,%3}, {%4,%5,%6,%7}, {%8,%9}, {%0,%1,%2,%3};"
                 : "+f"(c[0]), "+f"(c[1]), "+f"(c[2]), "+f"(c[3])
                 : "r"(a[0]), "r"(a[1]), "r"(a[2]), "r"(a[3]), "r"(b[0]), "r"(b[1]));
}
__device__ __forceinline__ void cp16(uint32_t d, const void* s) {
    asm volatile("cp.async.cg.shared.global [%0], [%1], 16;" :: "r"(d), "l"(s));
}
#define CP_COMMIT() asm volatile("cp.async.commit_group;" ::: "memory")

__device__ __forceinline__ uint32_t sw128(uint32_t o) { return o ^ ((o >> 3) & 0x70); }  // 128B rows
__device__ __forceinline__ uint32_t sw256(uint32_t o) { return o ^ ((o >> 4) & 0x70); }  // 256B rows

// pack two fp32 into fp16x2 hi, returning lo pair via out-param
__device__ __forceinline__ uint32_t split2(float x, float y, uint32_t& lo) {
    __half hx = __float2half_rn(x), hy = __float2half_rn(y);
    __half2 h2 = __halves2half2(hx, hy);
    __half2 l2 = __halves2half2(__float2half_rn(x - __half2float(hx)),
                                __float2half_rn(y - __half2float(hy)));
    lo = *(uint32_t*)&l2;
    return *(uint32_t*)&h2;
}
__device__ __forceinline__ uint32_t pack_h2(float x, float y) {
    __half2 h2 = __halves2half2(__float2half_rn(x), __float2half_rn(y));
    return *(uint32_t*)&h2;
}

// ================== 3-pass chunk-64 path (ntrelu only) ==================
// Stage: Ah @0 (16KB), Al @16K, Bh @32K, Bl @48K (BROWS=128)
template <int BROWS>
__device__ __forceinline__ void prefetch_c64(
    uint32_t st, const __half* Ah, const __half* Al,
    const __half* Bh, const __half* Bl, int ch, int tid)
{
    const int co = ch * 64;
#pragma unroll
    for (int i = tid; i < 1024; i += 256) {
        int r = i >> 3, sg = i & 7;
        uint32_t sw = sw128((uint32_t)(r * 128 + sg * 16));
        const size_t g = (size_t)r * ND + co + sg * 8;
        cp16(st + sw, Ah + g);
        cp16(st + 16384 + sw, Al + g);
    }
#pragma unroll
    for (int i = tid; i < BROWS * 8; i += 256) {
        int r = i >> 3, sg = i & 7;
        uint32_t sw = sw128((uint32_t)(r * 128 + sg * 16));
        const size_t g = (size_t)r * ND + co + sg * 8;
        cp16(st + 32768 + sw, Bh + g);
        cp16(st + 32768 + BROWS * 128 + sw, Bl + g);
    }
}

template <int MF, int NF, int BROWS>
__device__ __forceinline__ void mma_c64(float (&acc)[MF][NF][4], uint32_t st,
                                        int lane, int warpM, int warpN)
{
#pragma unroll
    for (int kk = 0; kk < 4; kk++) {
        uint32_t afH[MF][4], afL[MF][4];
#pragma unroll
        for (int mf = 0; mf < MF; mf++) {
            uint32_t row = warpM + mf * 16 + (lane & 15);
            uint32_t kb = kk * 16 + ((lane >> 4) << 3);
            uint32_t sw = sw128(row * 128 + kb * 2);
            ldm_x4(afH[mf], st + sw);
            ldm_x4(afL[mf], st + 16384 + sw);
        }
        uint32_t bfH[NF][2], bfL[NF][2];
#pragma unroll
        for (int nb = 0; nb < NF / 2; nb++) {
            uint32_t row = warpN + nb * 16 + (lane & 7) + ((lane >> 4) & 1) * 8;
            uint32_t kb = kk * 16 + ((lane >> 3) & 1) * 8;
            uint32_t sw = sw128(row * 128 + kb * 2);
            uint32_t t[4];
            ldm_x4(t, st + 32768 + sw);
            bfH[2 * nb][0] = t[0]; bfH[2 * nb][1] = t[1];
            bfH[2 * nb + 1][0] = t[2]; bfH[2 * nb + 1][1] = t[3];
            ldm_x4(t, st + 32768 + BROWS * 128 + sw);
            bfL[2 * nb][0] = t[0]; bfL[2 * nb][1] = t[1];
            bfL[2 * nb + 1][0] = t[2]; bfL[2 * nb + 1][1] = t[3];
        }
#pragma unroll
        for (int mf = 0; mf < MF; mf++)
#pragma unroll
            for (int nf = 0; nf < NF; nf++)
                mma_f16(acc[mf][nf], afH[mf], bfH[nf]);
#pragma unroll
        for (int mf = 0; mf < MF; mf++)
#pragma unroll
            for (int nf = 0; nf < NF; nf++)
                mma_f16(acc[mf][nf], afH[mf], bfL[nf]);
#pragma unroll
        for (int mf = 0; mf < MF; mf++)
#pragma unroll
            for (int nf = 0; nf < NF; nf++)
                mma_f16(acc[mf][nf], afL[mf], bfH[nf]);
    }
}

// ---------------- FFNN last layer (merged pred+span), 3-pass fp16 ----------------
__global__ __launch_bounds__(256, 1) void k_mma_ntrelu(const float* __restrict__ bpv,
                                                       const float* __restrict__ bav)
{
    extern __shared__ __align__(1024) char dsm[];
    const uint32_t sm = smem_to_u32(dsm);
    const int tid = threadIdx.x, lane = tid & 31, wid = tid >> 5;
    const int warpM = (wid >> 2) * 64, warpN = (wid & 3) * 32;
    const int isSpan = blockIdx.y >= 4;
    const int mBase = (isSpan ? (blockIdx.y - 4) : blockIdx.y) * 128;
    const int nBase = blockIdx.x * 128;
    const float* bias = isSpan ? bav : bpv;

    const __half* Ah = (isSpan ? g_span_h : g_pred_h) + (size_t)mBase * ND;
    const __half* Al = (isSpan ? g_span_l : g_pred_l) + (size_t)mBase * ND;
    const __half* Wh = (isSpan ? g_wa_h : g_wp_h) + (size_t)nBase * ND;
    const __half* Wl = (isSpan ? g_wa_l : g_wp_l) + (size_t)nBase * ND;
    float* hid = isSpan ? g_hid : g_hidp;

    const uint32_t STAGE = 65536u;
    float acc[4][4][4] = {};
    prefetch_c64<128>(sm, Ah, Al, Wh, Wl, 0, tid); CP_COMMIT();
    prefetch_c64<128>(sm + STAGE, Ah, Al, Wh, Wl, 1, tid); CP_COMMIT();
#pragma unroll 1
    for (int ch = 0; ch < 16; ch++) {
        asm volatile("cp.async.wait_group 1;");
        __syncthreads();
        int nx = ch + 2;
        if (nx < 16) prefetch_c64<128>(sm + (uint32_t)(nx % 3) * STAGE, Ah, Al, Wh, Wl, nx, tid);
        CP_COMMIT();
        mma_c64<4, 4, 128>(acc, sm + (uint32_t)(ch % 3) * STAGE, lane, warpM, warpN);
    }

#pragma unroll
    for (int mf = 0; mf < 4; mf++)
#pragma unroll
        for (int h = 0; h < 2; h++) {
            int row = mBase + warpM + mf * 16 + (lane >> 2) + h * 8;
            float* orow = hid + (size_t)row * ND;
#pragma unroll
            for (int nf = 0; nf < 4; nf++) {
                int col = nBase + warpN + nf * 8 + (lane & 3) * 2;
                float2 v;
                v.x = fmaxf(acc[mf][nf][2 * h + 0] + bias[col], 0.f);
                v.y = fmaxf(acc[mf][nf][2 * h + 1] + bias[col + 1], 0.f);
                *(float2*)(orow + col) = v;
            }
        }
}

// ================== Stage 1: 2-pass fp16, fused W1 split (hi only) ==================
// U[bp, l, e] = sum_d pred[bp, d] * W1[l, d, e];  C = (Ah+Al)·Bh, W1-lo dropped
#define U_ASTAGE 32768u
#define U_BOFF   98304u
#define U_BBUF   16384u

__device__ __forceinline__ void prefetch_A64(uint32_t st, const __half* Ah,
                                             const __half* Al, int ch, int tid)
{
    const int co = ch * 64;
#pragma unroll
    for (int i = tid; i < 1024; i += 256) {
        int r = i >> 3, sg = i & 7;
        uint32_t sw = sw128((uint32_t)(r * 128 + sg * 16));
        const size_t g = (size_t)r * ND + co + sg * 8;
        cp16(st + sw, Ah + g);
        cp16(st + 16384 + sw, Al + g);
    }
}

__device__ __forceinline__ void ldgB(float4 (&b)[8], const float* Wl, int ch, int tid) {
#pragma unroll
    for (int j = 0; j < 4; j++) {
        int g = tid + 256 * j;
        int r = g >> 4, cg = g & 15;
        const float* s = Wl + (size_t)(ch * 64 + r) * ND + cg * 8;
        b[2 * j]     = *(const float4*)s;
        b[2 * j + 1] = *(const float4*)(s + 4);
    }
}

// hi-only conversion + store: per j, 8 floats -> 4 half2 = uint4
__device__ __forceinline__ void stsB(char* bbase, const float4 (&b)[8], int tid) {
#pragma unroll
    for (int j = 0; j < 4; j++) {
        int g = tid + 256 * j;
        int r = g >> 4, cg = g & 15;
        uint32_t sw = sw256((uint32_t)(r * 256 + cg * 16));
        uint4 hi;
        hi.x = pack_h2(b[2 * j].x,     b[2 * j].y);
        hi.y = pack_h2(b[2 * j].z,     b[2 * j].w);
        hi.z = pack_h2(b[2 * j + 1].x, b[2 * j + 1].y);
        hi.w = pack_h2(b[2 * j + 1].z, b[2 * j + 1].w);
        *(uint4*)(bbase + sw) = hi;
    }
}

// 2 passes: afH.bfH + afL.bfH (B frags via ldmatrix.trans, K-major 256B rows)
template <int MF, int NF>
__device__ __forceinline__ void mma_chunk_u(float (&acc)[MF][NF][4], uint32_t stA,
                                            uint32_t bB, int lane, int warpM, int warpN)
{
#pragma unroll
    for (int kk = 0; kk < 4; kk++) {
        uint32_t afH[MF][4], afL[MF][4];
#pragma unroll
        for (int mf = 0; mf < MF; mf++) {
            uint32_t row = warpM + mf * 16 + (lane & 15);
            uint32_t kb = kk * 16 + ((lane >> 4) << 3);
            uint32_t sw = sw128(row * 128 + kb * 2);
            ldm_x4(afH[mf], stA + sw);
            ldm_x4(afL[mf], stA + 16384 + sw);
        }
        uint32_t bfH[NF][2];
#pragma unroll
        for (int nb = 0; nb < NF / 2; nb++) {
            uint32_t row = kk * 16 + ((lane >> 3) & 1) * 8 + (lane & 7);   // d within chunk
            uint32_t col = warpN + nb * 16 + ((lane >> 4) & 1) * 8;        // e within tile
            uint32_t sw = sw256(row * 256 + col * 2);
            uint32_t t[4];
            ldm_x4_t(t, bB + sw);
            bfH[2 * nb][0] = t[0]; bfH[2 * nb][1] = t[1];
            bfH[2 * nb + 1][0] = t[2]; bfH[2 * nb + 1][1] = t[3];
        }
#pragma unroll
        for (int mf = 0; mf < MF; mf++)
#pragma unroll
            for (int nf = 0; nf < NF; nf++)
                mma_f16(acc[mf][nf], afH[mf], bfH[nf]);
#pragma unroll
        for (int mf = 0; mf < MF; mf++)
#pragma unroll
            for (int nf = 0; nf < NF; nf++)
                mma_f16(acc[mf][nf], afL[mf], bfH[nf]);
    }
}

__global__ __launch_bounds__(256, 1) void k_u_mma(const float* __restrict__ W1)
{
    extern __shared__ __align__(1024) char dsm[];
    const uint32_t sm = smem_to_u32(dsm);
    const int tid = threadIdx.x, lane = tid & 31, wid = tid >> 5;
    const int warpM = (wid >> 2) * 64, warpN = (wid & 3) * 32;
    const int nBase = blockIdx.x * 128, mBase = blockIdx.y * 128, l = blockIdx.z;

    const __half* Ah = g_pred_h + (size_t)mBase * ND;
    const __half* Al = g_pred_l + (size_t)mBase * ND;
    const float* Wl = W1 + (size_t)l * ND * ND + nBase;   // + d*ND + e

    float4 breg[8];
    ldgB(breg, Wl, 0, tid);
    prefetch_A64(sm + 0 * U_ASTAGE, Ah, Al, 0, tid); CP_COMMIT();
    prefetch_A64(sm + 1 * U_ASTAGE, Ah, Al, 1, tid); CP_COMMIT();
    stsB(dsm + U_BOFF, breg, tid);

    float acc[4][4][4] = {};
#pragma unroll 1
    for (int ch = 0; ch < 16; ch++) {
        asm volatile("cp.async.wait_group 1;");
        __syncthreads();                              // publishes A(ch) + STS of B(ch)
        if (ch + 1 < 16) ldgB(breg, Wl, ch + 1, tid); // hidden under this chunk's MMA
        if (ch + 2 < 16) prefetch_A64(sm + (uint32_t)((ch + 2) % 3) * U_ASTAGE, Ah, Al, ch + 2, tid);
        CP_COMMIT();
        mma_chunk_u<4, 4>(acc, sm + (uint32_t)(ch % 3) * U_ASTAGE,
                          sm + U_BOFF + (uint32_t)(ch & 1) * U_BBUF, lane, warpM, warpN);
        if (ch + 1 < 16) stsB(dsm + U_BOFF + (size_t)((ch + 1) & 1) * U_BBUF, breg, tid);
    }

#pragma unroll
    for (int mf = 0; mf < 4; mf++)
#pragma unroll
        for (int h = 0; h < 2; h++) {
            int row = mBase + warpM + mf * 16 + (lane >> 2) + h * 8;
            size_t base = ((size_t)row * NL + l) * ND;
#pragma unroll
            for (int nf = 0; nf < 4; nf++) {
                int col = nBase + warpN + nf * 8 + (lane & 3) * 2;
                *(uint32_t*)(g_u + base + col) =
                    pack_h2(acc[mf][nf][2 * h + 0], acc[mf][nf][2 * h + 1]);
            }
        }
}

// ---------------- Stage 2 (2-pass: (Sh+Sl)·U) + full epilogue -> scores ----------------
// stage = Ah 16K + Al 16K + B 8K = 40960; 2 stages = 81920 (2 CTAs/SM)
#define F_STAGE 40960u

__device__ __forceinline__ void prefetch_fin(uint32_t st, const __half* Ah, const __half* Al,
                                             const __half* B, int ch, int tid)
{
    const int co = ch * 64;
#pragma unroll
    for (int i = tid; i < 1024; i += 256) {
        int r = i >> 3, sg = i & 7;
        uint32_t sw = sw128((uint32_t)(r * 128 + sg * 16));
        const size_t g = (size_t)r * ND + co + sg * 8;
        cp16(st + sw, Ah + g);
        cp16(st + 16384 + sw, Al + g);
    }
#pragma unroll
    for (int i = tid; i < 512; i += 256) {           // B: 64 rows x 8 sixteens
        int r = i >> 3, sg = i & 7;
        uint32_t sw = sw128((uint32_t)(r * 128 + sg * 16));
        cp16(st + 32768 + sw, B + (size_t)r * ND + co + sg * 8);
    }
}

template <int MF, int NF>
__device__ __forceinline__ void mma_fin(float (&acc)[MF][NF][4], uint32_t st,
                                        int lane, int warpM, int warpN)
{
#pragma unroll
    for (int kk = 0; kk < 4; kk++) {
        uint32_t afH[MF][4], afL[MF][4];
#pragma unroll
        for (int mf = 0; mf < MF; mf++) {
            uint32_t row = warpM + mf * 16 + (lane & 15);
            uint32_t kb = kk * 16 + ((lane >> 4) << 3);
            uint32_t sw = sw128(row * 128 + kb * 2);
            ldm_x4(afH[mf], st + sw);
            ldm_x4(afL[mf], st + 16384 + sw);
        }
        uint32_t bf[NF][2];
#pragma unroll
        for (int nb = 0; nb < NF / 2; nb++) {
            uint32_t row = warpN + nb * 16 + (lane & 7) + ((lane >> 4) & 1) * 8;
            uint32_t kb = kk * 16 + ((lane >> 3) & 1) * 8;
            uint32_t sw = sw128(row * 128 + kb * 2);
            uint32_t t[4];
            ldm_x4(t, st + 32768 + sw);
            bf[2 * nb][0] = t[0]; bf[2 * nb][1] = t[1];
            bf[2 * nb + 1][0] = t[2]; bf[2 * nb + 1][1] = t[3];
        }
#pragma unroll
        for (int mf = 0; mf < MF; mf++)
#pragma unroll
            for (int nf = 0; nf < NF; nf++)
                mma_f16(acc[mf][nf], afH[mf], bf[nf]);
#pragma unroll
        for (int mf = 0; mf < MF; mf++)
#pragma unroll
            for (int nf = 0; nf < NF; nf++)
                mma_f16(acc[mf][nf], afL[mf], bf[nf]);
    }
}

__global__ __launch_bounds__(256, 2) void k_final_mma(const float* __restrict__ bias,
                                                      float* __restrict__ out)
{
    extern __shared__ __align__(1024) char dsm[];
    const uint32_t sm = smem_to_u32(dsm);
    const int tid = threadIdx.x, lane = tid & 31, wid = tid >> 5;
    const int warpM = (wid >> 1) * 32, warpN = (wid & 1) * 32;
    const int mBase = blockIdx.x * 128, bp = blockIdx.y, b = bp >> 6;

    const __half* Ah = g_span_h + ((size_t)b * NS + mBase) * ND;
    const __half* Al = g_span_l + ((size_t)b * NS + mBase) * ND;
    const __half* B = g_u + (size_t)bp * NL * ND;

    float acc[2][4][4] = {};
    prefetch_fin(sm, Ah, Al, B, 0, tid); CP_COMMIT();
#pragma unroll 1
    for (int ch = 0; ch < 16; ch++) {
        asm volatile("cp.async.wait_group 0;");
        __syncthreads();
        int nx = ch + 1;
        if (nx < 16) prefetch_fin(sm + (uint32_t)(nx & 1) * F_STAGE, Ah, Al, B, nx, tid);
        CP_COMMIT();
        mma_fin<2, 4>(acc, sm + (uint32_t)(ch & 1) * F_STAGE, lane, warpM, warpN);
    }

    const float* p2 = g_p2 + (size_t)bp * NL;
#pragma unroll
    for (int mf = 0; mf < 2; mf++)
#pragma unroll
        for (int h = 0; h < 2; h++) {
            int s = mBase + warpM + mf * 16 + (lane >> 2) + h * 8;
            size_t srow = (size_t)b * NS + s;
            float add = g_psc[bp] + g_asc[srow];
            const float* s2 = g_s2 + srow * NL;
            float* orow = out + ((size_t)bp * NS + s) * NL;
#pragma unroll
            for (int nf = 0; nf < 4; nf++) {
                int col = warpN + nf * 8 + (lane & 3) * 2;
                float2 v;
                v.x = acc[mf][nf][2 * h + 0] + p2[col] + s2[col] + bias[col] + add;
                v.y = acc[mf][nf][2 * h + 1] + p2[col + 1] + s2[col + 1] + bias[col + 1] + add;
                if (col + 1 == NL - 1) v.y = 0.f;   // null-label column
                *(float2*)(orow + col) = v;
            }
        }
}

// ---------------- gather predicate rows + fp16 split ----------------
__global__ __launch_bounds__(256) void k_gather_split(const float* __restrict__ span,
                                                      const int* __restrict__ preds) {
    int bp = blockIdx.x;
    int b = bp / NP;
    int s = preds[bp];
    float4 v = ((const float4*)(span + ((size_t)b * NS + s) * ND))[threadIdx.x];
    ((float4*)(g_pred + (size_t)bp * ND))[threadIdx.x] = v;
    uint32_t lo0, lo1;
    uint32_t hi0 = split2(v.x, v.y, lo0);
    uint32_t hi1 = split2(v.z, v.w, lo1);
    uint32_t* ph = (uint32_t*)(g_pred_h + (size_t)bp * ND);
    uint32_t* pl = (uint32_t*)(g_pred_l + (size_t)bp * ND);
    ph[threadIdx.x * 2 + 0] = hi0;
    ph[threadIdx.x * 2 + 1] = hi1;
    pl[threadIdx.x * 2 + 0] = lo0;
    pl[threadIdx.x * 2 + 1] = lo1;
}

// ---------------- merged fp32 -> (hi, lo) fp16 split for span + Wp + Wa ----------------
#define N4_SPAN (BSD * ND / 4)    // 1048576
#define N4_W    (ND * ND / 4)     // 262144
__global__ __launch_bounds__(256) void k_splitall(const float* __restrict__ span,
                                                  const float* __restrict__ Wp,
                                                  const float* __restrict__ Wa) {
    int i = blockIdx.x * 256 + threadIdx.x;
    const float* x;
    __half *H, *L;
    int j;
    if (i < N4_SPAN)                { x = span; j = i;                     H = g_span_h; L = g_span_l; }
    else if (i < N4_SPAN + N4_W)    { x = Wp;   j = i - N4_SPAN;           H = g_wp_h;   L = g_wp_l; }
    else if (i < N4_SPAN + 2*N4_W)  { x = Wa;   j = i - N4_SPAN - N4_W;    H = g_wa_h;   L = g_wa_l; }
    else return;
    float4 v = ((const float4*)x)[j];
    uint32_t lo0, lo1;
    uint32_t hi0 = split2(v.x, v.y, lo0);
    uint32_t hi1 = split2(v.z, v.w, lo1);
    ((uint32_t*)H)[2 * j + 0] = hi0;
    ((uint32_t*)H)[2 * j + 1] = hi1;
    ((uint32_t*)L)[2 * j + 0] = lo0;
    ((uint32_t*)L)[2 * j + 1] = lo1;
}

// ---------------- merged row dot ----------------
__global__ __launch_bounds__(256) void k_rowdot(const float* __restrict__ wp,
                                                const float* __restrict__ wa) {
    int r = blockIdx.x;
    const int isPred = r >= BSD;
    const float* Hp = isPred ? (g_hidp + (size_t)(r - BSD) * ND) : (g_hid + (size_t)r * ND);
    const float* w = isPred ? wp : wa;
    float s = 0.f;
    for (int j = threadIdx.x; j < ND; j += 256) s = fmaf(Hp[j], w[j], s);
    __shared__ float red[256];
    red[threadIdx.x] = s;
    __syncthreads();
    for (int o = 128; o > 0; o >>= 1) {
        if (threadIdx.x < o) red[threadIdx.x] += red[threadIdx.x + o];
        __syncthreads();
    }
    if (threadIdx.x == 0) {
        if (isPred) g_psc[r - BSD] = red[0];
        else        g_asc[r] = red[0];
    }
}

// ---------------- merged NN GEMM M x 64, K=1024 ----------------
__global__ __launch_bounds__(256) void k_gemm_nn64(const float* __restrict__ span,
                                                   const float* __restrict__ W2) {
    const int isSpan = blockIdx.y >= 8;
    const float* A = isSpan ? span : g_pred;
    const float* Bw = W2 + (isSpan ? (size_t)ND * NL : 0);
    float* C = isSpan ? g_s2 : g_p2;
    const int rowBase = (isSpan ? (blockIdx.y - 8) : blockIdx.y) * 64;

    __shared__ float As[16][64];
    __shared__ float Bs[16][64];
    const int tid = threadIdx.x;
    const int tx = tid & 15, ty = tid >> 4;
    const int alr = tid >> 2;
    const int alc = (tid & 3) << 2;
    const float* Ap = A + (size_t)(rowBase + alr) * ND + alc;
    const int blr = tid >> 4;
    const int blc = (tid & 15) << 2;
    const float* Bp = Bw + (size_t)blr * NL + blc;

    float acc[4][4];
#pragma unroll
    for (int i = 0; i < 4; i++)
#pragma unroll
        for (int j = 0; j < 4; j++) acc[i][j] = 0.f;

    for (int k0 = 0; k0 < ND; k0 += 16) {
        float4 av = *(const float4*)(Ap + k0);
        As[alc + 0][alr] = av.x;
        As[alc + 1][alr] = av.y;
        As[alc + 2][alr] = av.z;
        As[alc + 3][alr] = av.w;
        float4 bv = *(const float4*)(Bp + (size_t)k0 * NL);
        *(float4*)&Bs[blr][blc] = bv;
        __syncthreads();
#pragma unroll
        for (int k = 0; k < 16; k++) {
            float4 a4 = *(const float4*)&As[k][ty * 4];
            float4 b4 = *(const float4*)&Bs[k][tx * 4];
            float a[4] = {a4.x, a4.y, a4.z, a4.w};
            float bb[4] = {b4.x, b4.y, b4.z, b4.w};
#pragma unroll
            for (int i = 0; i < 4; i++)
#pragma unroll
                for (int j = 0; j < 4; j++)
                    acc[i][j] = fmaf(a[i], bb[j], acc[i][j]);
        }
        __syncthreads();
    }
#pragma unroll
    for (int i = 0; i < 4; i++) {
        int row = rowBase + ty * 4 + i;
        *(float4*)(C + (size_t)row * NL + tx * 4) =
            make_float4(acc[i][0], acc[i][1], acc[i][2], acc[i][3]);
    }
}

// ---------------- labels cast + tail zero ----------------
__global__ void k_labels(const int* __restrict__ lab, float* __restrict__ out, int n) {
    int i = blockIdx.x * blockDim.x + threadIdx.x;
    if (i < n) out[i] = (float)lab[i];
}
__global__ void k_zero(float* __restrict__ out, int n) {
    int i = blockIdx.x * blockDim.x + threadIdx.x;
    if (i < n) out[i] = 0.f;
}

// ---------------- host ----------------
extern "C" void kernel_launch(void* const* d_in, const int* in_sizes, int n_in,
                              void* d_out, int out_size)
{
    const float* span   = (const float*)d_in[0];
    const int*   preds  = (const int*)d_in[1];
    const int*   labels = (const int*)d_in[2];
    // d_in[3] = len_info (dense, unused)
    // FFNN bug: only the LAST layer (index 1) of each stack matters.
    const float* Wp   = (const float*)d_in[4] + (size_t)ND * ND;
    const float* bpv  = (const float*)d_in[5] + ND;
    const float* Wa   = (const float*)d_in[6] + (size_t)ND * ND;
    const float* bav  = (const float*)d_in[7] + ND;
    const float* wp   = (const float*)d_in[8];
    const float* wa   = (const float*)d_in[9];
    const float* W1   = (const float*)d_in[10];
    const float* W2   = (const float*)d_in[11];
    const float* bias = (const float*)d_in[12];
    float* out = (float*)d_out;

    // second stream + fork/join events (created once; host resources, no device mem)
    static cudaStream_t sB = nullptr;
    static cudaEvent_t eG = nullptr, eB = nullptr;
    if (sB == nullptr) {
        cudaStreamCreateWithFlags(&sB, cudaStreamNonBlocking);
        cudaEventCreateWithFlags(&eG, cudaEventDisableTiming);
        cudaEventCreateWithFlags(&eB, cudaEventDisableTiming);
    }

    const int SMEM_NT  = 196608;   // ntrelu: 3 x 64KB (1 CTA/SM)
    const int SMEM_U   = 131072;   // u_mma:  3x32KB A + 2x16KB B-hi (1 CTA/SM)
    const int SMEM_FIN = 81920;    // final:  2 x 40KB (2 CTAs/SM)
    cudaFuncSetAttribute(k_mma_ntrelu, cudaFuncAttributeMaxDynamicSharedMemorySize, SMEM_NT);
    cudaFuncSetAttribute(k_u_mma,      cudaFuncAttributeMaxDynamicSharedMemorySize, SMEM_U);
    cudaFuncSetAttribute(k_final_mma,  cudaFuncAttributeMaxDynamicSharedMemorySize, SMEM_FIN);

    const int n_scores = NB * NP * NS * NL;
    const int n_lab = NB * NP * NS;

    // ---- stream 0 (capture stream): gather -> u_mma (the long pole) ----
    k_gather_split<<<BPD, 256>>>(span, preds);
    cudaEventRecord(eG, 0);
    k_u_mma<<<dim3(8, 4, 64), 256, SMEM_U>>>(W1);     // needs only pred_h/l + raw W1

    // ---- stream B: everything else, concurrent with u_mma ----
    cudaStreamWaitEvent(sB, eG, 0);
    k_splitall<<<(N4_SPAN + 2 * N4_W + 255) / 256, 256, 0, sB>>>(span, Wp, Wa);
    k_mma_ntrelu<<<dim3(8, 36), 256, SMEM_NT, sB>>>(bpv, bav);
    k_rowdot<<<BSD + BPD, 256, 0, sB>>>(wp, wa);
    k_gemm_nn64<<<dim3(1, 72), 256, 0, sB>>>(span, W2);
    if (out_size >= n_scores + n_lab)
        k_labels<<<(n_lab + 255) / 256, 256, 0, sB>>>(labels, out + n_scores, n_lab);
    {
        int written = (out_size >= n_scores + n_lab) ? n_scores + n_lab : n_scores;
        if (out_size > written) {
            int rem = out_size - written;
            k_zero<<<(rem + 255) / 256, 256, 0, sB>>>(out + written, rem);
        }
    }
    cudaEventRecord(eB, sB);

    // ---- join -> final ----
    cudaStreamWaitEvent(0, eB, 0);
    k_final_mma<<<dim3(4, 512), 256, SMEM_FIN>>>(bias, out);
}

// round 16
// speedup vs baseline: 1.7886x; 1.3192x over previous
#include <cuda_runtime.h>
#include <cuda_fp16.h>
#include <cstdint>

// Problem dims (fixed by reference)
#define NB 8
#define NP 64
#define NS 512
#define ND 1024
#define NL 64
#define BPD (NB * NP)   // 512
#define BSD (NB * NS)   // 4096

// ---------------- device scratch (static globals; no allocs allowed) ----------------
__device__ float g_pred[BPD * ND];
__device__ float g_hid[BSD * ND];     // span FFNN hidden
__device__ float g_hidp[BPD * ND];    // pred FFNN hidden
__device__ float g_psc[BPD];
__device__ float g_asc[BSD];
__device__ float g_p2[BPD * NL];
__device__ float g_s2[BSD * NL];
__device__ __half g_pred_h[BPD * ND];
__device__ __half g_span_h[BSD * ND], g_span_l[BSD * ND];
__device__ __half g_wp_h[ND * ND], g_wp_l[ND * ND];
__device__ __half g_wa_h[ND * ND], g_wa_l[ND * ND];
__device__ __half g_u[(size_t)BPD * NL * ND];   // U, fp16 hi only  [bp][l][e]

// ---------------- PTX helpers (plain sm_80+ features only) ----------------
__device__ __forceinline__ uint32_t smem_to_u32(const void* p) {
    uint32_t a;
    asm("{ .reg .u64 t; cvta.to.shared.u64 t, %1; cvt.u32.u64 %0, t; }" : "=r"(a) : "l"(p));
    return a;
}
__device__ __forceinline__ void ldm_x4(uint32_t* r, uint32_t a) {
    asm volatile("ldmatrix.sync.aligned.m8n8.x4.shared.b16 {%0,%1,%2,%3}, [%4];"
                 : "=r"(r[0]), "=r"(r[1]), "=r"(r[2]), "=r"(r[3]) : "r"(a));
}
__device__ __forceinline__ void ldm_x4_t(uint32_t* r, uint32_t a) {
    asm volatile("ldmatrix.sync.aligned.m8n8.x4.trans.shared.b16 {%0,%1,%2,%3}, [%4];"
                 : "=r"(r[0]), "=r"(r[1]), "=r"(r[2]), "=r"(r[3]) : "r"(a));
}
__device__ __forceinline__ void mma_f16(float* c, const uint32_t* a, const uint32_t* b) {
    asm volatile("mma.sync.aligned.m16n8k16.row.col.f32.f16.f16.f32 "
                 "{%0,%1,%2,%3}, {%4,%5,%6,%7}, {%8,%9}, {%0,%1,%2,%3};"
                 : "+f"(c[0]), "+f"(c[1]), "+f"(c[2]), "+f"(c[3])
                 : "r"(a[0]), "r"(a[1]), "r"(a[2]), "r"(a[3]), "r"(b[0]), "r"(b[1]));
}
__device__ __forceinline__ void cp16(uint32_t d, const void* s) {
    asm volatile("cp.async.cg.shared.global [%0], [%1], 16;" :: "r"(d), "l"(s));
}
#define CP_COMMIT() asm volatile("cp.async.commit_group;" ::: "memory")

__device__ __forceinline__ uint32_t sw128(uint32_t o) { return o ^ ((o >> 3) & 0x70); }  // 128B rows
__device__ __forceinline__ uint32_t sw256(uint32_t o) { return o ^ ((o >> 4) & 0x70); }  // 256B rows

// pack two fp32 into fp16x2 hi, returning lo pair via out-param
__device__ __forceinline__ uint32_t split2(float x, float y, uint32_t& lo) {
    __half hx = __float2half_rn(x), hy = __float2half_rn(y);
    __half2 h2 = __halves2half2(hx, hy);
    __half2 l2 = __halves2half2(__float2half_rn(x - __half2float(hx)),
                                __float2half_rn(y - __half2float(hy)));
    lo = *(uint32_t*)&l2;
    return *(uint32_t*)&h2;
}
__device__ __forceinline__ uint32_t pack_h2(float x, float y) {
    __half2 h2 = __halves2half2(__float2half_rn(x), __float2half_rn(y));
    return *(uint32_t*)&h2;
}

// ================== 3-pass chunk-64 path (ntrelu only) ==================
// Stage: Ah @0 (16KB), Al @16K, Bh @32K, Bl @48K (BROWS=128)
template <int BROWS>
__device__ __forceinline__ void prefetch_c64(
    uint32_t st, const __half* Ah, const __half* Al,
    const __half* Bh, const __half* Bl, int ch, int tid)
{
    const int co = ch * 64;
#pragma unroll
    for (int i = tid; i < 1024; i += 256) {
        int r = i >> 3, sg = i & 7;
        uint32_t sw = sw128((uint32_t)(r * 128 + sg * 16));
        const size_t g = (size_t)r * ND + co + sg * 8;
        cp16(st + sw, Ah + g);
        cp16(st + 16384 + sw, Al + g);
    }
#pragma unroll
    for (int i = tid; i < BROWS * 8; i += 256) {
        int r = i >> 3, sg = i & 7;
        uint32_t sw = sw128((uint32_t)(r * 128 + sg * 16));
        const size_t g = (size_t)r * ND + co + sg * 8;
        cp16(st + 32768 + sw, Bh + g);
        cp16(st + 32768 + BROWS * 128 + sw, Bl + g);
    }
}

template <int MF, int NF, int BROWS>
__device__ __forceinline__ void mma_c64(float (&acc)[MF][NF][4], uint32_t st,
                                        int lane, int warpM, int warpN)
{
#pragma unroll
    for (int kk = 0; kk < 4; kk++) {
        uint32_t afH[MF][4], afL[MF][4];
#pragma unroll
        for (int mf = 0; mf < MF; mf++) {
            uint32_t row = warpM + mf * 16 + (lane & 15);
            uint32_t kb = kk * 16 + ((lane >> 4) << 3);
            uint32_t sw = sw128(row * 128 + kb * 2);
            ldm_x4(afH[mf], st + sw);
            ldm_x4(afL[mf], st + 16384 + sw);
        }
        uint32_t bfH[NF][2], bfL[NF][2];
#pragma unroll
        for (int nb = 0; nb < NF / 2; nb++) {
            uint32_t row = warpN + nb * 16 + (lane & 7) + ((lane >> 4) & 1) * 8;
            uint32_t kb = kk * 16 + ((lane >> 3) & 1) * 8;
            uint32_t sw = sw128(row * 128 + kb * 2);
            uint32_t t[4];
            ldm_x4(t, st + 32768 + sw);
            bfH[2 * nb][0] = t[0]; bfH[2 * nb][1] = t[1];
            bfH[2 * nb + 1][0] = t[2]; bfH[2 * nb + 1][1] = t[3];
            ldm_x4(t, st + 32768 + BROWS * 128 + sw);
            bfL[2 * nb][0] = t[0]; bfL[2 * nb][1] = t[1];
            bfL[2 * nb + 1][0] = t[2]; bfL[2 * nb + 1][1] = t[3];
        }
#pragma unroll
        for (int mf = 0; mf < MF; mf++)
#pragma unroll
            for (int nf = 0; nf < NF; nf++)
                mma_f16(acc[mf][nf], afH[mf], bfH[nf]);
#pragma unroll
        for (int mf = 0; mf < MF; mf++)
#pragma unroll
            for (int nf = 0; nf < NF; nf++)
                mma_f16(acc[mf][nf], afH[mf], bfL[nf]);
#pragma unroll
        for (int mf = 0; mf < MF; mf++)
#pragma unroll
            for (int nf = 0; nf < NF; nf++)
                mma_f16(acc[mf][nf], afL[mf], bfH[nf]);
    }
}

// ---------------- FFNN last layer (merged pred+span), 3-pass fp16 ----------------
__global__ __launch_bounds__(256, 1) void k_mma_ntrelu(const float* __restrict__ bpv,
                                                       const float* __restrict__ bav)
{
    extern __shared__ __align__(1024) char dsm[];
    const uint32_t sm = smem_to_u32(dsm);
    const int tid = threadIdx.x, lane = tid & 31, wid = tid >> 5;
    const int warpM = (wid >> 2) * 64, warpN = (wid & 3) * 32;
    const int isSpan = blockIdx.y >= 4;
    const int mBase = (isSpan ? (blockIdx.y - 4) : blockIdx.y) * 128;
    const int nBase = blockIdx.x * 128;
    const float* bias = isSpan ? bav : bpv;

    // pred path: reuse span storage for lo?  pred-lo no longer exists; for the pred
    // FFNN we use pred_h as hi and a zero lo is wrong -> instead pred rows also live
    // in span (pred are gathered span rows), so use span_h/l via the gathered fp32?
    // Simpler: pred FFNN uses pred_h for BOTH hi passes is wrong. We keep the exact
    // R15 numerics by reading pred hi/lo from the span arrays through g_pred rows is
    // not index-stable. Solution: pred FFNN keeps 3-pass with per-row lo computed at
    // gather time into g_hidp as staging? -- Avoid complexity: pred FFNN error enters
    // only psc (additive, tiny); use hi-only A for pred tiles (2-pass A*Wh + A*Wl).
    const __half* Ah = (isSpan ? g_span_h : g_pred_h) + (size_t)mBase * ND;
    const __half* Al = (isSpan ? g_span_l : g_pred_h) + (size_t)mBase * ND; // pred: Al=Ah dummy
    const __half* Wh = (isSpan ? g_wa_h : g_wp_h) + (size_t)nBase * ND;
    const __half* Wl = (isSpan ? g_wa_l : g_wp_l) + (size_t)nBase * ND;
    float* hid = isSpan ? g_hid : g_hidp;

    const uint32_t STAGE = 65536u;
    float acc[4][4][4] = {};
    // For pred tiles (isSpan==0) the Al buffer duplicates Ah; we skip the Al*Bh pass
    // there to avoid double-counting (see pass-3 guard below).
    prefetch_c64<128>(sm, Ah, Al, Wh, Wl, 0, tid); CP_COMMIT();
    prefetch_c64<128>(sm + STAGE, Ah, Al, Wh, Wl, 1, tid); CP_COMMIT();
#pragma unroll 1
    for (int ch = 0; ch < 16; ch++) {
        asm volatile("cp.async.wait_group 1;");
        __syncthreads();
        int nx = ch + 2;
        if (nx < 16) prefetch_c64<128>(sm + (uint32_t)(nx % 3) * STAGE, Ah, Al, Wh, Wl, nx, tid);
        CP_COMMIT();
        // inline mma with conditional 3rd pass
        uint32_t st = sm + (uint32_t)(ch % 3) * STAGE;
#pragma unroll
        for (int kk = 0; kk < 4; kk++) {
            uint32_t afH[4][4], afL[4][4];
#pragma unroll
            for (int mf = 0; mf < 4; mf++) {
                uint32_t row = warpM + mf * 16 + (lane & 15);
                uint32_t kb = kk * 16 + ((lane >> 4) << 3);
                uint32_t sw = sw128(row * 128 + kb * 2);
                ldm_x4(afH[mf], st + sw);
                ldm_x4(afL[mf], st + 16384 + sw);
            }
            uint32_t bfH[4][2], bfL[4][2];
#pragma unroll
            for (int nb = 0; nb < 2; nb++) {
                uint32_t row = warpN + nb * 16 + (lane & 7) + ((lane >> 4) & 1) * 8;
                uint32_t kb = kk * 16 + ((lane >> 3) & 1) * 8;
                uint32_t sw = sw128(row * 128 + kb * 2);
                uint32_t t[4];
                ldm_x4(t, st + 32768 + sw);
                bfH[2 * nb][0] = t[0]; bfH[2 * nb][1] = t[1];
                bfH[2 * nb + 1][0] = t[2]; bfH[2 * nb + 1][1] = t[3];
                ldm_x4(t, st + 32768 + 16384 + sw);
                bfL[2 * nb][0] = t[0]; bfL[2 * nb][1] = t[1];
                bfL[2 * nb + 1][0] = t[2]; bfL[2 * nb + 1][1] = t[3];
            }
#pragma unroll
            for (int mf = 0; mf < 4; mf++)
#pragma unroll
                for (int nf = 0; nf < 4; nf++)
                    mma_f16(acc[mf][nf], afH[mf], bfH[nf]);
#pragma unroll
            for (int mf = 0; mf < 4; mf++)
#pragma unroll
                for (int nf = 0; nf < 4; nf++)
                    mma_f16(acc[mf][nf], afH[mf], bfL[nf]);
            if (isSpan) {
#pragma unroll
                for (int mf = 0; mf < 4; mf++)
#pragma unroll
                    for (int nf = 0; nf < 4; nf++)
                        mma_f16(acc[mf][nf], afL[mf], bfH[nf]);
            }
        }
    }

#pragma unroll
    for (int mf = 0; mf < 4; mf++)
#pragma unroll
        for (int h = 0; h < 2; h++) {
            int row = mBase + warpM + mf * 16 + (lane >> 2) + h * 8;
            float* orow = hid + (size_t)row * ND;
#pragma unroll
            for (int nf = 0; nf < 4; nf++) {
                int col = nBase + warpN + nf * 8 + (lane & 3) * 2;
                float2 v;
                v.x = fmaxf(acc[mf][nf][2 * h + 0] + bias[col], 0.f);
                v.y = fmaxf(acc[mf][nf][2 * h + 1] + bias[col + 1], 0.f);
                *(float2*)(orow + col) = v;
            }
        }
}

// ================== Stage 1: 1-pass fp16, fused W1 split (hi only) ==================
// U[bp, l, e] = sum_d pred[bp, d] * W1[l, d, e];  C = Ah·Bh
#define U_ASTAGE 16384u
#define U_BOFF   49152u
#define U_BBUF   16384u

__device__ __forceinline__ void prefetch_A64(uint32_t st, const __half* Ah, int ch, int tid)
{
    const int co = ch * 64;
#pragma unroll
    for (int i = tid; i < 1024; i += 256) {
        int r = i >> 3, sg = i & 7;
        uint32_t sw = sw128((uint32_t)(r * 128 + sg * 16));
        cp16(st + sw, Ah + (size_t)r * ND + co + sg * 8);
    }
}

__device__ __forceinline__ void ldgB(float4 (&b)[8], const float* Wl, int ch, int tid) {
#pragma unroll
    for (int j = 0; j < 4; j++) {
        int g = tid + 256 * j;
        int r = g >> 4, cg = g & 15;
        const float* s = Wl + (size_t)(ch * 64 + r) * ND + cg * 8;
        b[2 * j]     = *(const float4*)s;
        b[2 * j + 1] = *(const float4*)(s + 4);
    }
}

// hi-only conversion + store
__device__ __forceinline__ void stsB(char* bbase, const float4 (&b)[8], int tid) {
#pragma unroll
    for (int j = 0; j < 4; j++) {
        int g = tid + 256 * j;
        int r = g >> 4, cg = g & 15;
        uint32_t sw = sw256((uint32_t)(r * 256 + cg * 16));
        uint4 hi;
        hi.x = pack_h2(b[2 * j].x,     b[2 * j].y);
        hi.y = pack_h2(b[2 * j].z,     b[2 * j].w);
        hi.z = pack_h2(b[2 * j + 1].x, b[2 * j + 1].y);
        hi.w = pack_h2(b[2 * j + 1].z, b[2 * j + 1].w);
        *(uint4*)(bbase + sw) = hi;
    }
}

// 1 pass: afH.bfH (B frags via ldmatrix.trans, K-major 256B rows)
template <int MF, int NF>
__device__ __forceinline__ void mma_chunk_u(float (&acc)[MF][NF][4], uint32_t stA,
                                            uint32_t bB, int lane, int warpM, int warpN)
{
#pragma unroll
    for (int kk = 0; kk < 4; kk++) {
        uint32_t afH[MF][4];
#pragma unroll
        for (int mf = 0; mf < MF; mf++) {
            uint32_t row = warpM + mf * 16 + (lane & 15);
            uint32_t kb = kk * 16 + ((lane >> 4) << 3);
            uint32_t sw = sw128(row * 128 + kb * 2);
            ldm_x4(afH[mf], stA + sw);
        }
        uint32_t bfH[NF][2];
#pragma unroll
        for (int nb = 0; nb < NF / 2; nb++) {
            uint32_t row = kk * 16 + ((lane >> 3) & 1) * 8 + (lane & 7);   // d within chunk
            uint32_t col = warpN + nb * 16 + ((lane >> 4) & 1) * 8;        // e within tile
            uint32_t sw = sw256(row * 256 + col * 2);
            uint32_t t[4];
            ldm_x4_t(t, bB + sw);
            bfH[2 * nb][0] = t[0]; bfH[2 * nb][1] = t[1];
            bfH[2 * nb + 1][0] = t[2]; bfH[2 * nb + 1][1] = t[3];
        }
#pragma unroll
        for (int mf = 0; mf < MF; mf++)
#pragma unroll
            for (int nf = 0; nf < NF; nf++)
                mma_f16(acc[mf][nf], afH[mf], bfH[nf]);
    }
}

__global__ __launch_bounds__(256, 1) void k_u_mma(const float* __restrict__ W1)
{
    extern __shared__ __align__(1024) char dsm[];
    const uint32_t sm = smem_to_u32(dsm);
    const int tid = threadIdx.x, lane = tid & 31, wid = tid >> 5;
    const int warpM = (wid >> 2) * 64, warpN = (wid & 3) * 32;
    const int nBase = blockIdx.x * 128, mBase = blockIdx.y * 128, l = blockIdx.z;

    const __half* Ah = g_pred_h + (size_t)mBase * ND;
    const float* Wl = W1 + (size_t)l * ND * ND + nBase;   // + d*ND + e

    float4 breg[8];
    ldgB(breg, Wl, 0, tid);
    prefetch_A64(sm + 0 * U_ASTAGE, Ah, 0, tid); CP_COMMIT();
    prefetch_A64(sm + 1 * U_ASTAGE, Ah, 1, tid); CP_COMMIT();
    stsB(dsm + U_BOFF, breg, tid);

    float acc[4][4][4] = {};
#pragma unroll 1
    for (int ch = 0; ch < 16; ch++) {
        asm volatile("cp.async.wait_group 1;");
        __syncthreads();                              // publishes A(ch) + STS of B(ch)
        if (ch + 1 < 16) ldgB(breg, Wl, ch + 1, tid); // hidden under this chunk's MMA
        if (ch + 2 < 16) prefetch_A64(sm + (uint32_t)((ch + 2) % 3) * U_ASTAGE, Ah, ch + 2, tid);
        CP_COMMIT();
        mma_chunk_u<4, 4>(acc, sm + (uint32_t)(ch % 3) * U_ASTAGE,
                          sm + U_BOFF + (uint32_t)(ch & 1) * U_BBUF, lane, warpM, warpN);
        if (ch + 1 < 16) stsB(dsm + U_BOFF + (size_t)((ch + 1) & 1) * U_BBUF, breg, tid);
    }

#pragma unroll
    for (int mf = 0; mf < 4; mf++)
#pragma unroll
        for (int h = 0; h < 2; h++) {
            int row = mBase + warpM + mf * 16 + (lane >> 2) + h * 8;
            size_t base = ((size_t)row * NL + l) * ND;
#pragma unroll
            for (int nf = 0; nf < 4; nf++) {
                int col = nBase + warpN + nf * 8 + (lane & 3) * 2;
                *(uint32_t*)(g_u + base + col) =
                    pack_h2(acc[mf][nf][2 * h + 0], acc[mf][nf][2 * h + 1]);
            }
        }
}

// ---------------- Stage 2 (1-pass: Sh·U) + full epilogue -> scores ----------------
// stage = Ah 16K + B 8K = 24576; 2 stages = 49152 (2 CTAs/SM)
#define F_STAGE 24576u

__device__ __forceinline__ void prefetch_fin(uint32_t st, const __half* Ah,
                                             const __half* B, int ch, int tid)
{
    const int co = ch * 64;
#pragma unroll
    for (int i = tid; i < 1024; i += 256) {
        int r = i >> 3, sg = i & 7;
        uint32_t sw = sw128((uint32_t)(r * 128 + sg * 16));
        cp16(st + sw, Ah + (size_t)r * ND + co + sg * 8);
    }
#pragma unroll
    for (int i = tid; i < 512; i += 256) {           // B: 64 rows x 8 sixteens
        int r = i >> 3, sg = i & 7;
        uint32_t sw = sw128((uint32_t)(r * 128 + sg * 16));
        cp16(st + 16384 + sw, B + (size_t)r * ND + co + sg * 8);
    }
}

template <int MF, int NF>
__device__ __forceinline__ void mma_fin(float (&acc)[MF][NF][4], uint32_t st,
                                        int lane, int warpM, int warpN)
{
#pragma unroll
    for (int kk = 0; kk < 4; kk++) {
        uint32_t afH[MF][4];
#pragma unroll
        for (int mf = 0; mf < MF; mf++) {
            uint32_t row = warpM + mf * 16 + (lane & 15);
            uint32_t kb = kk * 16 + ((lane >> 4) << 3);
            uint32_t sw = sw128(row * 128 + kb * 2);
            ldm_x4(afH[mf], st + sw);
        }
        uint32_t bf[NF][2];
#pragma unroll
        for (int nb = 0; nb < NF / 2; nb++) {
            uint32_t row = warpN + nb * 16 + (lane & 7) + ((lane >> 4) & 1) * 8;
            uint32_t kb = kk * 16 + ((lane >> 3) & 1) * 8;
            uint32_t sw = sw128(row * 128 + kb * 2);
            uint32_t t[4];
            ldm_x4(t, st + 16384 + sw);
            bf[2 * nb][0] = t[0]; bf[2 * nb][1] = t[1];
            bf[2 * nb + 1][0] = t[2]; bf[2 * nb + 1][1] = t[3];
        }
#pragma unroll
        for (int mf = 0; mf < MF; mf++)
#pragma unroll
            for (int nf = 0; nf < NF; nf++)
                mma_f16(acc[mf][nf], afH[mf], bf[nf]);
    }
}

__global__ __launch_bounds__(256, 2) void k_final_mma(const float* __restrict__ bias,
                                                      float* __restrict__ out)
{
    extern __shared__ __align__(1024) char dsm[];
    const uint32_t sm = smem_to_u32(dsm);
    const int tid = threadIdx.x, lane = tid & 31, wid = tid >> 5;
    const int warpM = (wid >> 1) * 32, warpN = (wid & 1) * 32;
    const int mBase = blockIdx.x * 128, bp = blockIdx.y, b = bp >> 6;

    const __half* Ah = g_span_h + ((size_t)b * NS + mBase) * ND;
    const __half* B = g_u + (size_t)bp * NL * ND;

    float acc[2][4][4] = {};
    prefetch_fin(sm, Ah, B, 0, tid); CP_COMMIT();
#pragma unroll 1
    for (int ch = 0; ch < 16; ch++) {
        asm volatile("cp.async.wait_group 0;");
        __syncthreads();
        int nx = ch + 1;
        if (nx < 16) prefetch_fin(sm + (uint32_t)(nx & 1) * F_STAGE, Ah, B, nx, tid);
        CP_COMMIT();
        mma_fin<2, 4>(acc, sm + (uint32_t)(ch & 1) * F_STAGE, lane, warpM, warpN);
    }

    const float* p2 = g_p2 + (size_t)bp * NL;
#pragma unroll
    for (int mf = 0; mf < 2; mf++)
#pragma unroll
        for (int h = 0; h < 2; h++) {
            int s = mBase + warpM + mf * 16 + (lane >> 2) + h * 8;
            size_t srow = (size_t)b * NS + s;
            float add = g_psc[bp] + g_asc[srow];
            const float* s2 = g_s2 + srow * NL;
            float* orow = out + ((size_t)bp * NS + s) * NL;
#pragma unroll
            for (int nf = 0; nf < 4; nf++) {
                int col = warpN + nf * 8 + (lane & 3) * 2;
                float2 v;
                v.x = acc[mf][nf][2 * h + 0] + p2[col] + s2[col] + bias[col] + add;
                v.y = acc[mf][nf][2 * h + 1] + p2[col + 1] + s2[col + 1] + bias[col + 1] + add;
                if (col + 1 == NL - 1) v.y = 0.f;   // null-label column
                *(float2*)(orow + col) = v;
            }
        }
}

// ---------------- gather predicate rows (fp32 + fp16 hi) ----------------
__global__ __launch_bounds__(256) void k_gather_split(const float* __restrict__ span,
                                                      const int* __restrict__ preds) {
    int bp = blockIdx.x;
    int b = bp / NP;
    int s = preds[bp];
    float4 v = ((const float4*)(span + ((size_t)b * NS + s) * ND))[threadIdx.x];
    ((float4*)(g_pred + (size_t)bp * ND))[threadIdx.x] = v;
    uint32_t* ph = (uint32_t*)(g_pred_h + (size_t)bp * ND);
    ph[threadIdx.x * 2 + 0] = pack_h2(v.x, v.y);
    ph[threadIdx.x * 2 + 1] = pack_h2(v.z, v.w);
}

// ---------------- merged fp32 -> (hi, lo) fp16 split for span + Wp + Wa ----------------
#define N4_SPAN (BSD * ND / 4)    // 1048576
#define N4_W    (ND * ND / 4)     // 262144
__global__ __launch_bounds__(256) void k_splitall(const float* __restrict__ span,
                                                  const float* __restrict__ Wp,
                                                  const float* __restrict__ Wa) {
    int i = blockIdx.x * 256 + threadIdx.x;
    const float* x;
    __half *H, *L;
    int j;
    if (i < N4_SPAN)                { x = span; j = i;                     H = g_span_h; L = g_span_l; }
    else if (i < N4_SPAN + N4_W)    { x = Wp;   j = i - N4_SPAN;           H = g_wp_h;   L = g_wp_l; }
    else if (i < N4_SPAN + 2*N4_W)  { x = Wa;   j = i - N4_SPAN - N4_W;    H = g_wa_h;   L = g_wa_l; }
    else return;
    float4 v = ((const float4*)x)[j];
    uint32_t lo0, lo1;
    uint32_t hi0 = split2(v.x, v.y, lo0);
    uint32_t hi1 = split2(v.z, v.w, lo1);
    ((uint32_t*)H)[2 * j + 0] = hi0;
    ((uint32_t*)H)[2 * j + 1] = hi1;
    ((uint32_t*)L)[2 * j + 0] = lo0;
    ((uint32_t*)L)[2 * j + 1] = lo1;
}

// ---------------- merged row dot ----------------
__global__ __launch_bounds__(256) void k_rowdot(const float* __restrict__ wp,
                                                const float* __restrict__ wa) {
    int r = blockIdx.x;
    const int isPred = r >= BSD;
    const float* Hp = isPred ? (g_hidp + (size_t)(r - BSD) * ND) : (g_hid + (size_t)r * ND);
    const float* w = isPred ? wp : wa;
    float s = 0.f;
    for (int j = threadIdx.x; j < ND; j += 256) s = fmaf(Hp[j], w[j], s);
    __shared__ float red[256];
    red[threadIdx.x] = s;
    __syncthreads();
    for (int o = 128; o > 0; o >>= 1) {
        if (threadIdx.x < o) red[threadIdx.x] += red[threadIdx.x + o];
        __syncthreads();
    }
    if (threadIdx.x == 0) {
        if (isPred) g_psc[r - BSD] = red[0];
        else        g_asc[r] = red[0];
    }
}

// ---------------- merged NN GEMM M x 64, K=1024 ----------------
__global__ __launch_bounds__(256) void k_gemm_nn64(const float* __restrict__ span,
                                                   const float* __restrict__ W2) {
    const int isSpan = blockIdx.y >= 8;
    const float* A = isSpan ? span : g_pred;
    const float* Bw = W2 + (isSpan ? (size_t)ND * NL : 0);
    float* C = isSpan ? g_s2 : g_p2;
    const int rowBase = (isSpan ? (blockIdx.y - 8) : blockIdx.y) * 64;

    __shared__ float As[16][64];
    __shared__ float Bs[16][64];
    const int tid = threadIdx.x;
    const int tx = tid & 15, ty = tid >> 4;
    const int alr = tid >> 2;
    const int alc = (tid & 3) << 2;
    const float* Ap = A + (size_t)(rowBase + alr) * ND + alc;
    const int blr = tid >> 4;
    const int blc = (tid & 15) << 2;
    const float* Bp = Bw + (size_t)blr * NL + blc;

    float acc[4][4];
#pragma unroll
    for (int i = 0; i < 4; i++)
#pragma unroll
        for (int j = 0; j < 4; j++) acc[i][j] = 0.f;

    for (int k0 = 0; k0 < ND; k0 += 16) {
        float4 av = *(const float4*)(Ap + k0);
        As[alc + 0][alr] = av.x;
        As[alc + 1][alr] = av.y;
        As[alc + 2][alr] = av.z;
        As[alc + 3][alr] = av.w;
        float4 bv = *(const float4*)(Bp + (size_t)k0 * NL);
        *(float4*)&Bs[blr][blc] = bv;
        __syncthreads();
#pragma unroll
        for (int k = 0; k < 16; k++) {
            float4 a4 = *(const float4*)&As[k][ty * 4];
            float4 b4 = *(const float4*)&Bs[k][tx * 4];
            float a[4] = {a4.x, a4.y, a4.z, a4.w};
            float bb[4] = {b4.x, b4.y, b4.z, b4.w};
#pragma unroll
            for (int i = 0; i < 4; i++)
#pragma unroll
                for (int j = 0; j < 4; j++)
                    acc[i][j] = fmaf(a[i], bb[j], acc[i][j]);
        }
        __syncthreads();
    }
#pragma unroll
    for (int i = 0; i < 4; i++) {
        int row = rowBase + ty * 4 + i;
        *(float4*)(C + (size_t)row * NL + tx * 4) =
            make_float4(acc[i][0], acc[i][1], acc[i][2], acc[i][3]);
    }
}

// ---------------- labels cast + tail zero ----------------
__global__ void k_labels(const int* __restrict__ lab, float* __restrict__ out, int n) {
    int i = blockIdx.x * blockDim.x + threadIdx.x;
    if (i < n) out[i] = (float)lab[i];
}
__global__ void k_zero(float* __restrict__ out, int n) {
    int i = blockIdx.x * blockDim.x + threadIdx.x;
    if (i < n) out[i] = 0.f;
}

// ---------------- host ----------------
extern "C" void kernel_launch(void* const* d_in, const int* in_sizes, int n_in,
                              void* d_out, int out_size)
{
    const float* span   = (const float*)d_in[0];
    const int*   preds  = (const int*)d_in[1];
    const int*   labels = (const int*)d_in[2];
    // d_in[3] = len_info (dense, unused)
    // FFNN bug: only the LAST layer (index 1) of each stack matters.
    const float* Wp   = (const float*)d_in[4] + (size_t)ND * ND;
    const float* bpv  = (const float*)d_in[5] + ND;
    const float* Wa   = (const float*)d_in[6] + (size_t)ND * ND;
    const float* bav  = (const float*)d_in[7] + ND;
    const float* wp   = (const float*)d_in[8];
    const float* wa   = (const float*)d_in[9];
    const float* W1   = (const float*)d_in[10];
    const float* W2   = (const float*)d_in[11];
    const float* bias = (const float*)d_in[12];
    float* out = (float*)d_out;

    // second stream + fork/join events (created once; host resources, no device mem)
    static cudaStream_t sB = nullptr;
    static cudaEvent_t eG = nullptr, eB = nullptr;
    if (sB == nullptr) {
        cudaStreamCreateWithFlags(&sB, cudaStreamNonBlocking);
        cudaEventCreateWithFlags(&eG, cudaEventDisableTiming);
        cudaEventCreateWithFlags(&eB, cudaEventDisableTiming);
    }

    const int SMEM_NT  = 196608;   // ntrelu: 3 x 64KB (1 CTA/SM)
    const int SMEM_U   = 81920;    // u_mma:  3x16KB A-hi + 2x16KB B-hi
    const int SMEM_FIN = 49152;    // final:  2 x 24KB (2 CTAs/SM)
    cudaFuncSetAttribute(k_mma_ntrelu, cudaFuncAttributeMaxDynamicSharedMemorySize, SMEM_NT);
    cudaFuncSetAttribute(k_u_mma,      cudaFuncAttributeMaxDynamicSharedMemorySize, SMEM_U);
    cudaFuncSetAttribute(k_final_mma,  cudaFuncAttributeMaxDynamicSharedMemorySize, SMEM_FIN);

    const int n_scores = NB * NP * NS * NL;
    const int n_lab = NB * NP * NS;

    // ---- stream 0 (capture stream): gather -> u_mma (the long pole) ----
    k_gather_split<<<BPD, 256>>>(span, preds);
    cudaEventRecord(eG, 0);
    k_u_mma<<<dim3(8, 4, 64), 256, SMEM_U>>>(W1);     // needs only pred_h + raw W1

    // ---- stream B: everything else, concurrent with u_mma ----
    cudaStreamWaitEvent(sB, eG, 0);
    k_splitall<<<(N4_SPAN + 2 * N4_W + 255) / 256, 256, 0, sB>>>(span, Wp, Wa);
    k_mma_ntrelu<<<dim3(8, 36), 256, SMEM_NT, sB>>>(bpv, bav);
    k_rowdot<<<BSD + BPD, 256, 0, sB>>>(wp, wa);
    k_gemm_nn64<<<dim3(1, 72), 256, 0, sB>>>(span, W2);
    if (out_size >= n_scores + n_lab)
        k_labels<<<(n_lab + 255) / 256, 256, 0, sB>>>(labels, out + n_scores, n_lab);
    {
        int written = (out_size >= n_scores + n_lab) ? n_scores + n_lab : n_scores;
        if (out_size > written) {
            int rem = out_size - written;
            k_zero<<<(rem + 255) / 256, 256, 0, sB>>>(out + written, rem);
        }
    }
    cudaEventRecord(eB, sB);

    // ---- join -> final ----
    cudaStreamWaitEvent(0, eB, 0);
    k_final_mma<<<dim3(4, 512), 256, SMEM_FIN>>>(bias, out);
}

// round 17
// speedup vs baseline: 1.9045x; 1.0648x over previous
#include <cuda_runtime.h>
#include <cuda_fp16.h>
#include <cstdint>

// Problem dims (fixed by reference)
#define NB 8
#define NP 64
#define NS 512
#define ND 1024
#define NL 64
#define BPD (NB * NP)   // 512
#define BSD (NB * NS)   // 4096

// ---------------- device scratch (static globals; no allocs allowed) ----------------
__device__ float g_pred[BPD * ND];
__device__ float g_hid[BSD * ND];     // span FFNN hidden
__device__ float g_hidp[BPD * ND];    // pred FFNN hidden
__device__ float g_psc[BPD];
__device__ float g_asc[BSD];
__device__ float g_p2[BPD * NL];
__device__ float g_s2[BSD * NL];
__device__ __half g_pred_h[BPD * ND];
__device__ __half g_span_h[BSD * ND], g_span_l[BSD * ND];
__device__ __half g_wp_h[ND * ND], g_wp_l[ND * ND];
__device__ __half g_wa_h[ND * ND], g_wa_l[ND * ND];
__device__ __half g_u[(size_t)BPD * NL * ND];   // U, fp16 hi only  [bp][l][e]

// ---------------- PTX helpers (plain sm_80+ features only) ----------------
__device__ __forceinline__ uint32_t smem_to_u32(const void* p) {
    uint32_t a;
    asm("{ .reg .u64 t; cvta.to.shared.u64 t, %1; cvt.u32.u64 %0, t; }" : "=r"(a) : "l"(p));
    return a;
}
__device__ __forceinline__ void ldm_x4(uint32_t* r, uint32_t a) {
    asm volatile("ldmatrix.sync.aligned.m8n8.x4.shared.b16 {%0,%1,%2,%3}, [%4];"
                 : "=r"(r[0]), "=r"(r[1]), "=r"(r[2]), "=r"(r[3]) : "r"(a));
}
__device__ __forceinline__ void ldm_x4_t(uint32_t* r, uint32_t a) {
    asm volatile("ldmatrix.sync.aligned.m8n8.x4.trans.shared.b16 {%0,%1,%2,%3}, [%4];"
                 : "=r"(r[0]), "=r"(r[1]), "=r"(r[2]), "=r"(r[3]) : "r"(a));
}
__device__ __forceinline__ void mma_f16(float* c, const uint32_t* a, const uint32_t* b) {
    asm volatile("mma.sync.aligned.m16n8k16.row.col.f32.f16.f16.f32 "
                 "{%0,%1,%2,%3}, {%4,%5,%6,%7}, {%8,%9}, {%0,%1,%2,%3};"
                 : "+f"(c[0]), "+f"(c[1]), "+f"(c[2]), "+f"(c[3])
                 : "r"(a[0]), "r"(a[1]), "r"(a[2]), "r"(a[3]), "r"(b[0]), "r"(b[1]));
}
__device__ __forceinline__ void cp16(uint32_t d, const void* s) {
    asm volatile("cp.async.cg.shared.global [%0], [%1], 16;" :: "r"(d), "l"(s));
}
#define CP_COMMIT() asm volatile("cp.async.commit_group;" ::: "memory")

__device__ __forceinline__ uint32_t sw128(uint32_t o) { return o ^ ((o >> 3) & 0x70); }  // 128B rows
__device__ __forceinline__ uint32_t sw256(uint32_t o) { return o ^ ((o >> 4) & 0x70); }  // 256B rows

// pack two fp32 into fp16x2 hi, returning lo pair via out-param
__device__ __forceinline__ uint32_t split2(float x, float y, uint32_t& lo) {
    __half hx = __float2half_rn(x), hy = __float2half_rn(y);
    __half2 h2 = __halves2half2(hx, hy);
    __half2 l2 = __halves2half2(__float2half_rn(x - __half2float(hx)),
                                __float2half_rn(y - __half2float(hy)));
    lo = *(uint32_t*)&l2;
    return *(uint32_t*)&h2;
}
__device__ __forceinline__ uint32_t pack_h2(float x, float y) {
    __half2 h2 = __halves2half2(__float2half_rn(x), __float2half_rn(y));
    return *(uint32_t*)&h2;
}

// ================== chunk-64 prefetch (ntrelu: A hi/lo + B hi/lo) ==================
template <int BROWS>
__device__ __forceinline__ void prefetch_c64(
    uint32_t st, const __half* Ah, const __half* Al,
    const __half* Bh, const __half* Bl, int ch, int tid)
{
    const int co = ch * 64;
#pragma unroll
    for (int i = tid; i < 1024; i += 256) {
        int r = i >> 3, sg = i & 7;
        uint32_t sw = sw128((uint32_t)(r * 128 + sg * 16));
        const size_t g = (size_t)r * ND + co + sg * 8;
        cp16(st + sw, Ah + g);
        cp16(st + 16384 + sw, Al + g);
    }
#pragma unroll
    for (int i = tid; i < BROWS * 8; i += 256) {
        int r = i >> 3, sg = i & 7;
        uint32_t sw = sw128((uint32_t)(r * 128 + sg * 16));
        const size_t g = (size_t)r * ND + co + sg * 8;
        cp16(st + 32768 + sw, Bh + g);
        cp16(st + 32768 + BROWS * 128 + sw, Bl + g);
    }
}

// ---------------- FFNN last layer (merged pred+span), fp16 ----------------
// span tiles: 3 passes (Ah.Bh + Ah.Bl + Al.Bh); pred tiles: 2 passes (A hi only)
__global__ __launch_bounds__(256, 1) void k_mma_ntrelu(const float* __restrict__ bpv,
                                                       const float* __restrict__ bav)
{
    extern __shared__ __align__(1024) char dsm[];
    const uint32_t sm = smem_to_u32(dsm);
    const int tid = threadIdx.x, lane = tid & 31, wid = tid >> 5;
    const int warpM = (wid >> 2) * 64, warpN = (wid & 3) * 32;
    const int isSpan = blockIdx.y >= 4;
    const int mBase = (isSpan ? (blockIdx.y - 4) : blockIdx.y) * 128;
    const int nBase = blockIdx.x * 128;
    const float* bias = isSpan ? bav : bpv;

    const __half* Ah = (isSpan ? g_span_h : g_pred_h) + (size_t)mBase * ND;
    const __half* Al = (isSpan ? g_span_l : g_pred_h) + (size_t)mBase * ND; // pred: dummy (pass skipped)
    const __half* Wh = (isSpan ? g_wa_h : g_wp_h) + (size_t)nBase * ND;
    const __half* Wl = (isSpan ? g_wa_l : g_wp_l) + (size_t)nBase * ND;
    float* hid = isSpan ? g_hid : g_hidp;

    const uint32_t STAGE = 65536u;
    float acc[4][4][4] = {};
    prefetch_c64<128>(sm, Ah, Al, Wh, Wl, 0, tid); CP_COMMIT();
    prefetch_c64<128>(sm + STAGE, Ah, Al, Wh, Wl, 1, tid); CP_COMMIT();
#pragma unroll 1
    for (int ch = 0; ch < 16; ch++) {
        asm volatile("cp.async.wait_group 1;");
        __syncthreads();
        int nx = ch + 2;
        if (nx < 16) prefetch_c64<128>(sm + (uint32_t)(nx % 3) * STAGE, Ah, Al, Wh, Wl, nx, tid);
        CP_COMMIT();
        uint32_t st = sm + (uint32_t)(ch % 3) * STAGE;
#pragma unroll
        for (int kk = 0; kk < 4; kk++) {
            uint32_t afH[4][4], afL[4][4];
#pragma unroll
            for (int mf = 0; mf < 4; mf++) {
                uint32_t row = warpM + mf * 16 + (lane & 15);
                uint32_t kb = kk * 16 + ((lane >> 4) << 3);
                uint32_t sw = sw128(row * 128 + kb * 2);
                ldm_x4(afH[mf], st + sw);
                ldm_x4(afL[mf], st + 16384 + sw);
            }
            uint32_t bfH[4][2], bfL[4][2];
#pragma unroll
            for (int nb = 0; nb < 2; nb++) {
                uint32_t row = warpN + nb * 16 + (lane & 7) + ((lane >> 4) & 1) * 8;
                uint32_t kb = kk * 16 + ((lane >> 3) & 1) * 8;
                uint32_t sw = sw128(row * 128 + kb * 2);
                uint32_t t[4];
                ldm_x4(t, st + 32768 + sw);
                bfH[2 * nb][0] = t[0]; bfH[2 * nb][1] = t[1];
                bfH[2 * nb + 1][0] = t[2]; bfH[2 * nb + 1][1] = t[3];
                ldm_x4(t, st + 32768 + 16384 + sw);
                bfL[2 * nb][0] = t[0]; bfL[2 * nb][1] = t[1];
                bfL[2 * nb + 1][0] = t[2]; bfL[2 * nb + 1][1] = t[3];
            }
#pragma unroll
            for (int mf = 0; mf < 4; mf++)
#pragma unroll
                for (int nf = 0; nf < 4; nf++)
                    mma_f16(acc[mf][nf], afH[mf], bfH[nf]);
#pragma unroll
            for (int mf = 0; mf < 4; mf++)
#pragma unroll
                for (int nf = 0; nf < 4; nf++)
                    mma_f16(acc[mf][nf], afH[mf], bfL[nf]);
            if (isSpan) {
#pragma unroll
                for (int mf = 0; mf < 4; mf++)
#pragma unroll
                    for (int nf = 0; nf < 4; nf++)
                        mma_f16(acc[mf][nf], afL[mf], bfH[nf]);
            }
        }
    }

#pragma unroll
    for (int mf = 0; mf < 4; mf++)
#pragma unroll
        for (int h = 0; h < 2; h++) {
            int row = mBase + warpM + mf * 16 + (lane >> 2) + h * 8;
            float* orow = hid + (size_t)row * ND;
#pragma unroll
            for (int nf = 0; nf < 4; nf++) {
                int col = nBase + warpN + nf * 8 + (lane & 3) * 2;
                float2 v;
                v.x = fmaxf(acc[mf][nf][2 * h + 0] + bias[col], 0.f);
                v.y = fmaxf(acc[mf][nf][2 * h + 1] + bias[col + 1], 0.f);
                *(float2*)(orow + col) = v;
            }
        }
}

// ================== Stage 1: 1-pass fp16, fused W1 split, 2 CTAs/SM ==================
// U[bp, l, e] = sum_d pred_h[bp, d] * W1_h[l, d, e]
// B staged in half-chunks (rows 0-31 / 32-63) aligned with kk halves to cut regs.
#define U_ASTAGE 16384u
#define U_BOFF   49152u
#define U_BBUF   16384u

__device__ __forceinline__ void prefetch_A64(uint32_t st, const __half* Ah, int ch, int tid)
{
    const int co = ch * 64;
#pragma unroll
    for (int i = tid; i < 1024; i += 256) {
        int r = i >> 3, sg = i & 7;
        uint32_t sw = sw128((uint32_t)(r * 128 + sg * 16));
        cp16(st + sw, Ah + (size_t)r * ND + co + sg * 8);
    }
}

// half H of the 64x128 fp32 W1 chunk: rows [H*32, H*32+32)
template <int H>
__device__ __forceinline__ void ldgB_half(float4 (&b)[4], const float* Wl, int ch, int tid) {
#pragma unroll
    for (int j = 0; j < 2; j++) {
        int g = tid + 256 * (2 * H + j) - 512 * H;   // g in [512H, 512H+512)
        int r = (g + 512 * H) >> 4;                  // rows 32H..32H+31
        int cg = (g + 512 * H) & 15;
        (void)g;
        const float* s = Wl + (size_t)(ch * 64 + r) * ND + cg * 8;
        b[2 * j]     = *(const float4*)s;
        b[2 * j + 1] = *(const float4*)(s + 4);
    }
}

template <int H>
__device__ __forceinline__ void stsB_half(char* bbase, const float4 (&b)[4], int tid) {
#pragma unroll
    for (int j = 0; j < 2; j++) {
        int g = tid + 256 * j + 512 * H;             // 512H..512H+511
        int r = g >> 4, cg = g & 15;
        uint32_t sw = sw256((uint32_t)(r * 256 + cg * 16));
        uint4 hi;
        hi.x = pack_h2(b[2 * j].x,     b[2 * j].y);
        hi.y = pack_h2(b[2 * j].z,     b[2 * j].w);
        hi.z = pack_h2(b[2 * j + 1].x, b[2 * j + 1].y);
        hi.w = pack_h2(b[2 * j + 1].z, b[2 * j + 1].w);
        *(uint4*)(bbase + sw) = hi;
    }
}

// kk-half of the 1-pass MMA: kk in {2*KH, 2*KH+1}
template <int KH>
__device__ __forceinline__ void mma_u_half(float (&acc)[4][4][4], uint32_t stA,
                                           uint32_t bB, int lane, int warpM, int warpN)
{
#pragma unroll
    for (int kk = 2 * KH; kk < 2 * KH + 2; kk++) {
        uint32_t afH[4][4];
#pragma unroll
        for (int mf = 0; mf < 4; mf++) {
            uint32_t row = warpM + mf * 16 + (lane & 15);
            uint32_t kb = kk * 16 + ((lane >> 4) << 3);
            uint32_t sw = sw128(row * 128 + kb * 2);
            ldm_x4(afH[mf], stA + sw);
        }
        uint32_t bfH[4][2];
#pragma unroll
        for (int nb = 0; nb < 2; nb++) {
            uint32_t row = kk * 16 + ((lane >> 3) & 1) * 8 + (lane & 7);   // d within chunk
            uint32_t col = warpN + nb * 16 + ((lane >> 4) & 1) * 8;        // e within tile
            uint32_t sw = sw256(row * 256 + col * 2);
            uint32_t t[4];
            ldm_x4_t(t, bB + sw);
            bfH[2 * nb][0] = t[0]; bfH[2 * nb][1] = t[1];
            bfH[2 * nb + 1][0] = t[2]; bfH[2 * nb + 1][1] = t[3];
        }
#pragma unroll
        for (int mf = 0; mf < 4; mf++)
#pragma unroll
            for (int nf = 0; nf < 4; nf++)
                mma_f16(acc[mf][nf], afH[mf], bfH[nf]);
    }
}

__global__ __launch_bounds__(256, 2) void k_u_mma(const float* __restrict__ W1)
{
    extern __shared__ __align__(1024) char dsm[];
    const uint32_t sm = smem_to_u32(dsm);
    const int tid = threadIdx.x, lane = tid & 31, wid = tid >> 5;
    const int warpM = (wid >> 2) * 64, warpN = (wid & 3) * 32;
    const int nBase = blockIdx.x * 128, mBase = blockIdx.y * 128, l = blockIdx.z;

    const __half* Ah = g_pred_h + (size_t)mBase * ND;
    const float* Wl = W1 + (size_t)l * ND * ND + nBase;   // + d*ND + e

    float4 breg[4];
    // prologue: B(0) both halves; A(0), A(1)
    ldgB_half<0>(breg, Wl, 0, tid);
    prefetch_A64(sm + 0 * U_ASTAGE, Ah, 0, tid); CP_COMMIT();
    stsB_half<0>(dsm + U_BOFF, breg, tid);
    ldgB_half<1>(breg, Wl, 0, tid);
    prefetch_A64(sm + 1 * U_ASTAGE, Ah, 1, tid); CP_COMMIT();
    stsB_half<1>(dsm + U_BOFF, breg, tid);

    float acc[4][4][4] = {};
#pragma unroll 1
    for (int ch = 0; ch < 16; ch++) {
        asm volatile("cp.async.wait_group 1;");
        __syncthreads();                              // publishes A(ch) + STS of B(ch)
        if (ch + 1 < 16) ldgB_half<0>(breg, Wl, ch + 1, tid);
        if (ch + 2 < 16) prefetch_A64(sm + (uint32_t)((ch + 2) % 3) * U_ASTAGE, Ah, ch + 2, tid);
        CP_COMMIT();
        const uint32_t stA = sm + (uint32_t)(ch % 3) * U_ASTAGE;
        const uint32_t bB = sm + U_BOFF + (uint32_t)(ch & 1) * U_BBUF;
        char* nextB = dsm + U_BOFF + (size_t)((ch + 1) & 1) * U_BBUF;
        mma_u_half<0>(acc, stA, bB, lane, warpM, warpN);
        if (ch + 1 < 16) {
            stsB_half<0>(nextB, breg, tid);
            ldgB_half<1>(breg, Wl, ch + 1, tid);
        }
        mma_u_half<1>(acc, stA, bB, lane, warpM, warpN);
        if (ch + 1 < 16) stsB_half<1>(nextB, breg, tid);
    }

#pragma unroll
    for (int mf = 0; mf < 4; mf++)
#pragma unroll
        for (int h = 0; h < 2; h++) {
            int row = mBase + warpM + mf * 16 + (lane >> 2) + h * 8;
            size_t base = ((size_t)row * NL + l) * ND;
#pragma unroll
            for (int nf = 0; nf < 4; nf++) {
                int col = nBase + warpN + nf * 8 + (lane & 3) * 2;
                *(uint32_t*)(g_u + base + col) =
                    pack_h2(acc[mf][nf][2 * h + 0], acc[mf][nf][2 * h + 1]);
            }
        }
}

// ---------------- Stage 2 (1-pass: Sh·U) + full epilogue -> scores ----------------
// stage = Ah 16K + B 8K = 24576; 2 stages = 49152 (2 CTAs/SM)
#define F_STAGE 24576u

__device__ __forceinline__ void prefetch_fin(uint32_t st, const __half* Ah,
                                             const __half* B, int ch, int tid)
{
    const int co = ch * 64;
#pragma unroll
    for (int i = tid; i < 1024; i += 256) {
        int r = i >> 3, sg = i & 7;
        uint32_t sw = sw128((uint32_t)(r * 128 + sg * 16));
        cp16(st + sw, Ah + (size_t)r * ND + co + sg * 8);
    }
#pragma unroll
    for (int i = tid; i < 512; i += 256) {           // B: 64 rows x 8 sixteens
        int r = i >> 3, sg = i & 7;
        uint32_t sw = sw128((uint32_t)(r * 128 + sg * 16));
        cp16(st + 16384 + sw, B + (size_t)r * ND + co + sg * 8);
    }
}

template <int MF, int NF>
__device__ __forceinline__ void mma_fin(float (&acc)[MF][NF][4], uint32_t st,
                                        int lane, int warpM, int warpN)
{
#pragma unroll
    for (int kk = 0; kk < 4; kk++) {
        uint32_t afH[MF][4];
#pragma unroll
        for (int mf = 0; mf < MF; mf++) {
            uint32_t row = warpM + mf * 16 + (lane & 15);
            uint32_t kb = kk * 16 + ((lane >> 4) << 3);
            uint32_t sw = sw128(row * 128 + kb * 2);
            ldm_x4(afH[mf], st + sw);
        }
        uint32_t bf[NF][2];
#pragma unroll
        for (int nb = 0; nb < NF / 2; nb++) {
            uint32_t row = warpN + nb * 16 + (lane & 7) + ((lane >> 4) & 1) * 8;
            uint32_t kb = kk * 16 + ((lane >> 3) & 1) * 8;
            uint32_t sw = sw128(row * 128 + kb * 2);
            uint32_t t[4];
            ldm_x4(t, st + 16384 + sw);
            bf[2 * nb][0] = t[0]; bf[2 * nb][1] = t[1];
            bf[2 * nb + 1][0] = t[2]; bf[2 * nb + 1][1] = t[3];
        }
#pragma unroll
        for (int mf = 0; mf < MF; mf++)
#pragma unroll
            for (int nf = 0; nf < NF; nf++)
                mma_f16(acc[mf][nf], afH[mf], bf[nf]);
    }
}

__global__ __launch_bounds__(256, 2) void k_final_mma(const float* __restrict__ bias,
                                                      float* __restrict__ out)
{
    extern __shared__ __align__(1024) char dsm[];
    const uint32_t sm = smem_to_u32(dsm);
    const int tid = threadIdx.x, lane = tid & 31, wid = tid >> 5;
    const int warpM = (wid >> 1) * 32, warpN = (wid & 1) * 32;
    const int mBase = blockIdx.x * 128, bp = blockIdx.y, b = bp >> 6;

    const __half* Ah = g_span_h + ((size_t)b * NS + mBase) * ND;
    const __half* B = g_u + (size_t)bp * NL * ND;

    float acc[2][4][4] = {};
    prefetch_fin(sm, Ah, B, 0, tid); CP_COMMIT();
#pragma unroll 1
    for (int ch = 0; ch < 16; ch++) {
        asm volatile("cp.async.wait_group 0;");
        __syncthreads();
        int nx = ch + 1;
        if (nx < 16) prefetch_fin(sm + (uint32_t)(nx & 1) * F_STAGE, Ah, B, nx, tid);
        CP_COMMIT();
        mma_fin<2, 4>(acc, sm + (uint32_t)(ch & 1) * F_STAGE, lane, warpM, warpN);
    }

    const float* p2 = g_p2 + (size_t)bp * NL;
#pragma unroll
    for (int mf = 0; mf < 2; mf++)
#pragma unroll
        for (int h = 0; h < 2; h++) {
            int s = mBase + warpM + mf * 16 + (lane >> 2) + h * 8;
            size_t srow = (size_t)b * NS + s;
            float add = g_psc[bp] + g_asc[srow];
            const float* s2 = g_s2 + srow * NL;
            float* orow = out + ((size_t)bp * NS + s) * NL;
#pragma unroll
            for (int nf = 0; nf < 4; nf++) {
                int col = warpN + nf * 8 + (lane & 3) * 2;
                float2 v;
                v.x = acc[mf][nf][2 * h + 0] + p2[col] + s2[col] + bias[col] + add;
                v.y = acc[mf][nf][2 * h + 1] + p2[col + 1] + s2[col + 1] + bias[col + 1] + add;
                if (col + 1 == NL - 1) v.y = 0.f;   // null-label column
                *(float2*)(orow + col) = v;
            }
        }
}

// ---------------- gather predicate rows (fp32 + fp16 hi) ----------------
__global__ __launch_bounds__(256) void k_gather_split(const float* __restrict__ span,
                                                      const int* __restrict__ preds) {
    int bp = blockIdx.x;
    int b = bp / NP;
    int s = preds[bp];
    float4 v = ((const float4*)(span + ((size_t)b * NS + s) * ND))[threadIdx.x];
    ((float4*)(g_pred + (size_t)bp * ND))[threadIdx.x] = v;
    uint32_t* ph = (uint32_t*)(g_pred_h + (size_t)bp * ND);
    ph[threadIdx.x * 2 + 0] = pack_h2(v.x, v.y);
    ph[threadIdx.x * 2 + 1] = pack_h2(v.z, v.w);
}

// ---------------- merged fp32 -> (hi, lo) fp16 split for span + Wp + Wa ----------------
#define N4_SPAN (BSD * ND / 4)    // 1048576
#define N4_W    (ND * ND / 4)     // 262144
__global__ __launch_bounds__(256) void k_splitall(const float* __restrict__ span,
                                                  const float* __restrict__ Wp,
                                                  const float* __restrict__ Wa) {
    int i = blockIdx.x * 256 + threadIdx.x;
    const float* x;
    __half *H, *L;
    int j;
    if (i < N4_SPAN)                { x = span; j = i;                     H = g_span_h; L = g_span_l; }
    else if (i < N4_SPAN + N4_W)    { x = Wp;   j = i - N4_SPAN;           H = g_wp_h;   L = g_wp_l; }
    else if (i < N4_SPAN + 2*N4_W)  { x = Wa;   j = i - N4_SPAN - N4_W;    H = g_wa_h;   L = g_wa_l; }
    else return;
    float4 v = ((const float4*)x)[j];
    uint32_t lo0, lo1;
    uint32_t hi0 = split2(v.x, v.y, lo0);
    uint32_t hi1 = split2(v.z, v.w, lo1);
    ((uint32_t*)H)[2 * j + 0] = hi0;
    ((uint32_t*)H)[2 * j + 1] = hi1;
    ((uint32_t*)L)[2 * j + 0] = lo0;
    ((uint32_t*)L)[2 * j + 1] = lo1;
}

// ---------------- merged row dot ----------------
__global__ __launch_bounds__(256) void k_rowdot(const float* __restrict__ wp,
                                                const float* __restrict__ wa) {
    int r = blockIdx.x;
    const int isPred = r >= BSD;
    const float* Hp = isPred ? (g_hidp + (size_t)(r - BSD) * ND) : (g_hid + (size_t)r * ND);
    const float* w = isPred ? wp : wa;
    float s = 0.f;
    for (int j = threadIdx.x; j < ND; j += 256) s = fmaf(Hp[j], w[j], s);
    __shared__ float red[256];
    red[threadIdx.x] = s;
    __syncthreads();
    for (int o = 128; o > 0; o >>= 1) {
        if (threadIdx.x < o) red[threadIdx.x] += red[threadIdx.x + o];
        __syncthreads();
    }
    if (threadIdx.x == 0) {
        if (isPred) g_psc[r - BSD] = red[0];
        else        g_asc[r] = red[0];
    }
}

// ---------------- merged NN GEMM M x 64, K=1024 ----------------
__global__ __launch_bounds__(256) void k_gemm_nn64(const float* __restrict__ span,
                                                   const float* __restrict__ W2) {
    const int isSpan = blockIdx.y >= 8;
    const float* A = isSpan ? span : g_pred;
    const float* Bw = W2 + (isSpan ? (size_t)ND * NL : 0);
    float* C = isSpan ? g_s2 : g_p2;
    const int rowBase = (isSpan ? (blockIdx.y - 8) : blockIdx.y) * 64;

    __shared__ float As[16][64];
    __shared__ float Bs[16][64];
    const int tid = threadIdx.x;
    const int tx = tid & 15, ty = tid >> 4;
    const int alr = tid >> 2;
    const int alc = (tid & 3) << 2;
    const float* Ap = A + (size_t)(rowBase + alr) * ND + alc;
    const int blr = tid >> 4;
    const int blc = (tid & 15) << 2;
    const float* Bp = Bw + (size_t)blr * NL + blc;

    float acc[4][4];
#pragma unroll
    for (int i = 0; i < 4; i++)
#pragma unroll
        for (int j = 0; j < 4; j++) acc[i][j] = 0.f;

    for (int k0 = 0; k0 < ND; k0 += 16) {
        float4 av = *(const float4*)(Ap + k0);
        As[alc + 0][alr] = av.x;
        As[alc + 1][alr] = av.y;
        As[alc + 2][alr] = av.z;
        As[alc + 3][alr] = av.w;
        float4 bv = *(const float4*)(Bp + (size_t)k0 * NL);
        *(float4*)&Bs[blr][blc] = bv;
        __syncthreads();
#pragma unroll
        for (int k = 0; k < 16; k++) {
            float4 a4 = *(const float4*)&As[k][ty * 4];
            float4 b4 = *(const float4*)&Bs[k][tx * 4];
            float a[4] = {a4.x, a4.y, a4.z, a4.w};
            float bb[4] = {b4.x, b4.y, b4.z, b4.w};
#pragma unroll
            for (int i = 0; i < 4; i++)
#pragma unroll
                for (int j = 0; j < 4; j++)
                    acc[i][j] = fmaf(a[i], bb[j], acc[i][j]);
        }
        __syncthreads();
    }
#pragma unroll
    for (int i = 0; i < 4; i++) {
        int row = rowBase + ty * 4 + i;
        *(float4*)(C + (size_t)row * NL + tx * 4) =
            make_float4(acc[i][0], acc[i][1], acc[i][2], acc[i][3]);
    }
}

// ---------------- labels cast + tail zero ----------------
__global__ void k_labels(const int* __restrict__ lab, float* __restrict__ out, int n) {
    int i = blockIdx.x * blockDim.x + threadIdx.x;
    if (i < n) out[i] = (float)lab[i];
}
__global__ void k_zero(float* __restrict__ out, int n) {
    int i = blockIdx.x * blockDim.x + threadIdx.x;
    if (i < n) out[i] = 0.f;
}

// ---------------- host ----------------
extern "C" void kernel_launch(void* const* d_in, const int* in_sizes, int n_in,
                              void* d_out, int out_size)
{
    const float* span   = (const float*)d_in[0];
    const int*   preds  = (const int*)d_in[1];
    const int*   labels = (const int*)d_in[2];
    // d_in[3] = len_info (dense, unused)
    // FFNN bug: only the LAST layer (index 1) of each stack matters.
    const float* Wp   = (const float*)d_in[4] + (size_t)ND * ND;
    const float* bpv  = (const float*)d_in[5] + ND;
    const float* Wa   = (const float*)d_in[6] + (size_t)ND * ND;
    const float* bav  = (const float*)d_in[7] + ND;
    const float* wp   = (const float*)d_in[8];
    const float* wa   = (const float*)d_in[9];
    const float* W1   = (const float*)d_in[10];
    const float* W2   = (const float*)d_in[11];
    const float* bias = (const float*)d_in[12];
    float* out = (float*)d_out;

    // second stream + fork/join events (created once; host resources, no device mem)
    static cudaStream_t sB = nullptr;
    static cudaEvent_t eG = nullptr, eB = nullptr;
    if (sB == nullptr) {
        cudaStreamCreateWithFlags(&sB, cudaStreamNonBlocking);
        cudaEventCreateWithFlags(&eG, cudaEventDisableTiming);
        cudaEventCreateWithFlags(&eB, cudaEventDisableTiming);
    }

    const int SMEM_NT  = 196608;   // ntrelu: 3 x 64KB (1 CTA/SM)
    const int SMEM_U   = 81920;    // u_mma:  3x16KB A-hi + 2x16KB B-hi (2 CTAs/SM)
    const int SMEM_FIN = 49152;    // final:  2 x 24KB (2 CTAs/SM)
    cudaFuncSetAttribute(k_mma_ntrelu, cudaFuncAttributeMaxDynamicSharedMemorySize, SMEM_NT);
    cudaFuncSetAttribute(k_u_mma,      cudaFuncAttributeMaxDynamicSharedMemorySize, SMEM_U);
    cudaFuncSetAttribute(k_final_mma,  cudaFuncAttributeMaxDynamicSharedMemorySize, SMEM_FIN);

    const int n_scores = NB * NP * NS * NL;
    const int n_lab = NB * NP * NS;

    // ---- stream 0 (capture stream): gather -> u_mma (the long pole) ----
    k_gather_split<<<BPD, 256>>>(span, preds);
    cudaEventRecord(eG, 0);
    k_u_mma<<<dim3(8, 4, 64), 256, SMEM_U>>>(W1);     // needs only pred_h + raw W1

    // ---- stream B: everything else, concurrent with u_mma ----
    cudaStreamWaitEvent(sB, eG, 0);
    k_splitall<<<(N4_SPAN + 2 * N4_W + 255) / 256, 256, 0, sB>>>(span, Wp, Wa);
    k_mma_ntrelu<<<dim3(8, 36), 256, SMEM_NT, sB>>>(bpv, bav);
    k_rowdot<<<BSD + BPD, 256, 0, sB>>>(wp, wa);
    k_gemm_nn64<<<dim3(1, 72), 256, 0, sB>>>(span, W2);
    if (out_size >= n_scores + n_lab)
        k_labels<<<(n_lab + 255) / 256, 256, 0, sB>>>(labels, out + n_scores, n_lab);
    {
        int written = (out_size >= n_scores + n_lab) ? n_scores + n_lab : n_scores;
        if (out_size > written) {
            int rem = out_size - written;
            k_zero<<<(rem + 255) / 256, 256, 0, sB>>>(out + written, rem);
        }
    }
    cudaEventRecord(eB, sB);

    // ---- join -> final ----
    cudaStreamWaitEvent(0, eB, 0);
    k_final_mma<<<dim3(4, 512), 256, SMEM_FIN>>>(bias, out);
}